// round 1
// baseline (speedup 1.0000x reference)
#include <cuda_runtime.h>
#include <math.h>

// Problem constants
#define DIMD 2048
#define HID 3840
#define NTOK 8192
#define NEXP 4
#define EPSV 1e-5f

// Tiling
#define BM 128
#define BN 128
#define BK 8
#define TM 8
#define TN 8
#define BMP (BM + 4)
#define BNP (BN + 4)
#define MAX_TILES (NTOK / BM + NEXP)

// Scratch (device globals: allocation-free)
__device__ float g_h[(size_t)NTOK * HID];   // SwiGLU hidden, sorted token order
__device__ float g_y[(size_t)NTOK * DIMD];  // down-proj output, sorted token order
__device__ int   g_perm[NTOK];              // sorted-pos -> token index
__device__ int   g_tile_e[MAX_TILES];
__device__ int   g_tile_row0[MAX_TILES];
__device__ int   g_tile_rows[MAX_TILES];
__device__ int   g_ntiles;

// ---------------------------------------------------------------------------
// Routing: histogram -> offsets -> tile table -> scatter permutation
// ---------------------------------------------------------------------------
__global__ void route_kernel(const int* __restrict__ ids) {
    __shared__ int cnt[NEXP];
    __shared__ int cur[NEXP];
    int tid = threadIdx.x;
    if (tid < NEXP) cnt[tid] = 0;
    __syncthreads();
    for (int t = tid; t < NTOK; t += blockDim.x)
        atomicAdd(&cnt[ids[t]], 1);
    __syncthreads();
    if (tid == 0) {
        int o = 0, nt = 0;
        for (int e = 0; e < NEXP; e++) {
            cur[e] = o;
            int c = cnt[e];
            for (int r = 0; r < c; r += BM) {
                g_tile_e[nt] = e;
                g_tile_row0[nt] = o + r;
                g_tile_rows[nt] = (c - r) < BM ? (c - r) : BM;
                nt++;
            }
            o += c;
        }
        g_ntiles = nt;
    }
    __syncthreads();
    for (int t = tid; t < NTOK; t += blockDim.x) {
        int e = ids[t];
        int p = atomicAdd(&cur[e], 1);
        g_perm[p] = t;
    }
}

// ---------------------------------------------------------------------------
// GEMM1: h[srow, n] = silu(x[tok]·w1[e,n,:]) * (x[tok]·w3[e,n,:])
//   A gathered via g_perm. Dual-B shares the A tile.
// ---------------------------------------------------------------------------
__global__ __launch_bounds__(256) void gemm1_kernel(
    const float* __restrict__ x,
    const float* __restrict__ w1,
    const float* __restrict__ w3)
{
    int tileId = blockIdx.y;
    if (tileId >= g_ntiles) return;
    const int e    = g_tile_e[tileId];
    const int row0 = g_tile_row0[tileId];
    const int rows = g_tile_rows[tileId];
    const int bn0  = blockIdx.x * BN;
    const int tid  = threadIdx.x;

    __shared__ float As [2][BK][BMP];
    __shared__ float B1s[2][BK][BNP];
    __shared__ float B3s[2][BK][BNP];
    __shared__ int   rowTok[BM];

    if (tid < BM) {
        int r = tid < rows ? tid : rows - 1;
        rowTok[tid] = g_perm[row0 + r];
    }
    __syncthreads();

    const int lr = tid >> 1;          // 0..127
    const int lc = (tid & 1) * 4;     // 0 or 4
    const float* aptr  = x  + (size_t)rowTok[lr] * DIMD + lc;
    const float* b1ptr = w1 + ((size_t)e * HID + bn0 + lr) * DIMD + lc;
    const float* b3ptr = w3 + ((size_t)e * HID + bn0 + lr) * DIMD + lc;

#define G1_LOAD(buf, k0) do {                                               \
        float4 av  = *(const float4*)(aptr  + (k0));                        \
        float4 bv1 = *(const float4*)(b1ptr + (k0));                        \
        float4 bv3 = *(const float4*)(b3ptr + (k0));                        \
        As [buf][lc+0][lr]=av.x;  As [buf][lc+1][lr]=av.y;                  \
        As [buf][lc+2][lr]=av.z;  As [buf][lc+3][lr]=av.w;                  \
        B1s[buf][lc+0][lr]=bv1.x; B1s[buf][lc+1][lr]=bv1.y;                 \
        B1s[buf][lc+2][lr]=bv1.z; B1s[buf][lc+3][lr]=bv1.w;                 \
        B3s[buf][lc+0][lr]=bv3.x; B3s[buf][lc+1][lr]=bv3.y;                 \
        B3s[buf][lc+2][lr]=bv3.z; B3s[buf][lc+3][lr]=bv3.w;                 \
    } while (0)

    float accg[TM][TN] = {};
    float accu[TM][TN] = {};
    const int ty = (tid >> 4) * TM;
    const int tx = (tid & 15) * TN;

    G1_LOAD(0, 0);
    __syncthreads();

    const int nk = DIMD / BK;
    for (int kk = 0; kk < nk; kk++) {
        int buf = kk & 1;
        if (kk + 1 < nk) G1_LOAD(buf ^ 1, (kk + 1) * BK);
#pragma unroll
        for (int k = 0; k < BK; k++) {
            float a[TM], b1[TN], b3[TN];
            *(float4*)&a[0]  = *(const float4*)&As [buf][k][ty];
            *(float4*)&a[4]  = *(const float4*)&As [buf][k][ty + 4];
            *(float4*)&b1[0] = *(const float4*)&B1s[buf][k][tx];
            *(float4*)&b1[4] = *(const float4*)&B1s[buf][k][tx + 4];
            *(float4*)&b3[0] = *(const float4*)&B3s[buf][k][tx];
            *(float4*)&b3[4] = *(const float4*)&B3s[buf][k][tx + 4];
#pragma unroll
            for (int i = 0; i < TM; i++)
#pragma unroll
                for (int j = 0; j < TN; j++) {
                    accg[i][j] += a[i] * b1[j];
                    accu[i][j] += a[i] * b3[j];
                }
        }
        __syncthreads();
    }

    // Epilogue: SwiGLU, store to g_h (sorted order)
#pragma unroll
    for (int i = 0; i < TM; i++) {
        int m = ty + i;
        if (m < rows) {
            float* hp = g_h + (size_t)(row0 + m) * HID + bn0 + tx;
#pragma unroll
            for (int jj = 0; jj < TN; jj += 4) {
                float4 hv;
                float gx;
                gx = accg[i][jj+0]; hv.x = gx / (1.f + expf(-gx)) * accu[i][jj+0];
                gx = accg[i][jj+1]; hv.y = gx / (1.f + expf(-gx)) * accu[i][jj+1];
                gx = accg[i][jj+2]; hv.z = gx / (1.f + expf(-gx)) * accu[i][jj+2];
                gx = accg[i][jj+3]; hv.w = gx / (1.f + expf(-gx)) * accu[i][jj+3];
                *(float4*)(hp + jj) = hv;
            }
        }
    }
#undef G1_LOAD
}

// ---------------------------------------------------------------------------
// GEMM2: y[srow, n] = h[srow,:] · w2[e,n,:]
// ---------------------------------------------------------------------------
__global__ __launch_bounds__(256) void gemm2_kernel(const float* __restrict__ w2)
{
    int tileId = blockIdx.y;
    if (tileId >= g_ntiles) return;
    const int e    = g_tile_e[tileId];
    const int row0 = g_tile_row0[tileId];
    const int rows = g_tile_rows[tileId];
    const int bn0  = blockIdx.x * BN;
    const int tid  = threadIdx.x;

    __shared__ float As[2][BK][BMP];
    __shared__ float Bs[2][BK][BNP];

    const int lr = tid >> 1;
    const int lc = (tid & 1) * 4;
    int ar = lr < rows ? lr : rows - 1;
    const float* aptr = g_h + (size_t)(row0 + ar) * HID + lc;
    const float* bptr = w2 + ((size_t)e * DIMD + bn0 + lr) * HID + lc;

#define G2_LOAD(buf, k0) do {                                               \
        float4 av = *(const float4*)(aptr + (k0));                          \
        float4 bv = *(const float4*)(bptr + (k0));                          \
        As[buf][lc+0][lr]=av.x; As[buf][lc+1][lr]=av.y;                     \
        As[buf][lc+2][lr]=av.z; As[buf][lc+3][lr]=av.w;                     \
        Bs[buf][lc+0][lr]=bv.x; Bs[buf][lc+1][lr]=bv.y;                     \
        Bs[buf][lc+2][lr]=bv.z; Bs[buf][lc+3][lr]=bv.w;                     \
    } while (0)

    float acc[TM][TN] = {};
    const int ty = (tid >> 4) * TM;
    const int tx = (tid & 15) * TN;

    G2_LOAD(0, 0);
    __syncthreads();

    const int nk = HID / BK;
    for (int kk = 0; kk < nk; kk++) {
        int buf = kk & 1;
        if (kk + 1 < nk) G2_LOAD(buf ^ 1, (kk + 1) * BK);
#pragma unroll
        for (int k = 0; k < BK; k++) {
            float a[TM], b[TN];
            *(float4*)&a[0] = *(const float4*)&As[buf][k][ty];
            *(float4*)&a[4] = *(const float4*)&As[buf][k][ty + 4];
            *(float4*)&b[0] = *(const float4*)&Bs[buf][k][tx];
            *(float4*)&b[4] = *(const float4*)&Bs[buf][k][tx + 4];
#pragma unroll
            for (int i = 0; i < TM; i++)
#pragma unroll
                for (int j = 0; j < TN; j++)
                    acc[i][j] += a[i] * b[j];
        }
        __syncthreads();
    }

#pragma unroll
    for (int i = 0; i < TM; i++) {
        int m = ty + i;
        if (m < rows) {
            float* yp = g_y + (size_t)(row0 + m) * DIMD + bn0 + tx;
#pragma unroll
            for (int jj = 0; jj < TN; jj += 4) {
                float4 v;
                v.x = acc[i][jj+0]; v.y = acc[i][jj+1];
                v.z = acc[i][jj+2]; v.w = acc[i][jj+3];
                *(float4*)(yp + jj) = v;
            }
        }
    }
#undef G2_LOAD
}

// ---------------------------------------------------------------------------
// RMSNorm + scale by norm_w[e] + scatter back to token order
// ---------------------------------------------------------------------------
__global__ __launch_bounds__(256) void norm_kernel(
    const float* __restrict__ norm_w,
    const int* __restrict__ ids,
    float* __restrict__ out)
{
    const int i   = blockIdx.x;       // sorted row
    const int tid = threadIdx.x;
    const int tok = g_perm[i];
    const int e   = ids[tok];
    const float* yr = g_y + (size_t)i * DIMD;

    float s = 0.f;
#pragma unroll
    for (int j = tid * 4; j < DIMD; j += 256 * 4) {
        float4 v = *(const float4*)(yr + j);
        s += v.x * v.x + v.y * v.y + v.z * v.z + v.w * v.w;
    }
#pragma unroll
    for (int o = 16; o; o >>= 1) s += __shfl_xor_sync(0xFFFFFFFFu, s, o);

    __shared__ float ws[8];
    __shared__ float stot;
    if ((tid & 31) == 0) ws[tid >> 5] = s;
    __syncthreads();
    if (tid == 0) {
        float t = 0.f;
#pragma unroll
        for (int w = 0; w < 8; w++) t += ws[w];
        stot = t;
    }
    __syncthreads();

    const float scale = rsqrtf(stot * (1.0f / DIMD) + EPSV);
    const float* nw = norm_w + (size_t)e * DIMD;
    float* op = out + (size_t)tok * DIMD;
#pragma unroll
    for (int j = tid * 4; j < DIMD; j += 256 * 4) {
        float4 v = *(const float4*)(yr + j);
        float4 w = *(const float4*)(nw + j);
        float4 r;
        r.x = v.x * scale * w.x;
        r.y = v.y * scale * w.y;
        r.z = v.z * scale * w.z;
        r.w = v.w * scale * w.w;
        *(float4*)(op + j) = r;
    }
}

// ---------------------------------------------------------------------------
extern "C" void kernel_launch(void* const* d_in, const int* in_sizes, int n_in,
                              void* d_out, int out_size) {
    const float* x      = (const float*)d_in[0];
    const float* w1     = (const float*)d_in[1];
    const float* w2     = (const float*)d_in[2];
    const float* w3     = (const float*)d_in[3];
    const float* norm_w = (const float*)d_in[4];
    const int*   ids    = (const int*)d_in[5];
    float* out = (float*)d_out;

    route_kernel<<<1, 256>>>(ids);

    dim3 g1(HID / BN, MAX_TILES);
    gemm1_kernel<<<g1, 256>>>(x, w1, w3);

    dim3 g2(DIMD / BN, MAX_TILES);
    gemm2_kernel<<<g2, 256>>>(w2);

    norm_kernel<<<NTOK, 256>>>(norm_w, ids, out);
}

// round 3
// speedup vs baseline: 3.7081x; 3.7081x over previous
#include <cuda_runtime.h>
#include <cuda_bf16.h>
#include <math.h>
#include <stdint.h>

// ---------------------------------------------------------------------------
// Problem constants
// ---------------------------------------------------------------------------
#define DIMD 2048
#define HID  3840
#define NTOK 8192
#define NEXP 4
#define EPSV 1e-5f
#define BM 128
#define BN 128
#define MAX_TILES (NTOK / BM + NEXP)

#define G1_NK (DIMD / 64)   // 32 K-chunks of 64
#define G2_NK (HID / 64)    // 60 K-chunks of 64
#define TILEB 16384         // one 128x64 bf16 tile = 16KB (128B rows, SW128)

// SW128 swizzle (Swizzle<3,4,3>) on byte offsets within a tile
#define SW(o) ((o) ^ (((o) >> 3) & 0x70))

// ---------------------------------------------------------------------------
// Scratch (device globals: allocation-free)
// ---------------------------------------------------------------------------
__device__ __nv_bfloat16 g_x_hi[(size_t)NTOK * DIMD];
__device__ __nv_bfloat16 g_x_lo[(size_t)NTOK * DIMD];
__device__ __nv_bfloat16 g_w1_hi[(size_t)NEXP * HID * DIMD];
__device__ __nv_bfloat16 g_w1_lo[(size_t)NEXP * HID * DIMD];
__device__ __nv_bfloat16 g_w3_hi[(size_t)NEXP * HID * DIMD];
__device__ __nv_bfloat16 g_w3_lo[(size_t)NEXP * HID * DIMD];
__device__ __nv_bfloat16 g_w2_hi[(size_t)NEXP * DIMD * HID];
__device__ __nv_bfloat16 g_w2_lo[(size_t)NEXP * DIMD * HID];
__device__ __nv_bfloat16 g_h_hi[(size_t)NTOK * HID];
__device__ __nv_bfloat16 g_h_lo[(size_t)NTOK * HID];
__device__ float g_y[(size_t)NTOK * DIMD];
__device__ int   g_perm[NTOK];
__device__ int   g_tile_e[MAX_TILES];
__device__ int   g_tile_row0[MAX_TILES];
__device__ int   g_tile_rows[MAX_TILES];
__device__ int   g_ntiles;

// ---------------------------------------------------------------------------
// PTX helpers (all sm_80-baseline: legal at compute_103 plain)
// ---------------------------------------------------------------------------
__device__ __forceinline__ uint32_t smem_u32(const void* p) {
    uint32_t a;
    asm("{ .reg .u64 t; cvta.to.shared.u64 t, %1; cvt.u32.u64 %0, t; }" : "=r"(a) : "l"(p));
    return a;
}
__device__ __forceinline__ void cpasync16(uint32_t dst, const void* src) {
    asm volatile("cp.async.cg.shared.global [%0], [%1], 16;" :: "r"(dst), "l"(src) : "memory");
}
__device__ __forceinline__ void cp_commit() {
    asm volatile("cp.async.commit_group;" ::: "memory");
}
__device__ __forceinline__ void cp_wait1() {
    asm volatile("cp.async.wait_group 1;" ::: "memory");
}
__device__ __forceinline__ void cp_wait0() {
    asm volatile("cp.async.wait_group 0;" ::: "memory");
}
__device__ __forceinline__ void ldsm4(uint32_t* r, uint32_t addr) {
    asm volatile("ldmatrix.sync.aligned.m8n8.x4.shared.b16 {%0,%1,%2,%3}, [%4];"
                 : "=r"(r[0]), "=r"(r[1]), "=r"(r[2]), "=r"(r[3]) : "r"(addr));
}
__device__ __forceinline__ void mma16816(float* d, const uint32_t* a, const uint32_t* b) {
    asm volatile("mma.sync.aligned.m16n8k16.row.col.f32.bf16.bf16.f32 "
                 "{%0,%1,%2,%3}, {%4,%5,%6,%7}, {%8,%9}, {%0,%1,%2,%3};"
                 : "+f"(d[0]), "+f"(d[1]), "+f"(d[2]), "+f"(d[3])
                 : "r"(a[0]), "r"(a[1]), "r"(a[2]), "r"(a[3]), "r"(b[0]), "r"(b[1]));
}

// ---------------------------------------------------------------------------
// Routing
// ---------------------------------------------------------------------------
__global__ void route_kernel(const int* __restrict__ ids) {
    __shared__ int cnt[NEXP];
    __shared__ int cur[NEXP];
    int tid = threadIdx.x;
    if (tid < NEXP) cnt[tid] = 0;
    __syncthreads();
    for (int t = tid; t < NTOK; t += blockDim.x) atomicAdd(&cnt[ids[t]], 1);
    __syncthreads();
    if (tid == 0) {
        int o = 0, nt = 0;
        for (int e = 0; e < NEXP; e++) {
            cur[e] = o;
            int c = cnt[e];
            for (int r = 0; r < c; r += BM) {
                g_tile_e[nt] = e;
                g_tile_row0[nt] = o + r;
                g_tile_rows[nt] = (c - r) < BM ? (c - r) : BM;
                nt++;
            }
            o += c;
        }
        g_ntiles = nt;
    }
    __syncthreads();
    for (int t = tid; t < NTOK; t += blockDim.x) {
        int p = atomicAdd(&cur[ids[t]], 1);
        g_perm[p] = t;
    }
}

// ---------------------------------------------------------------------------
// fp32 -> bf16 hi/lo split. which: 0=w1, 1=w3, 2=w2, 3=x
// ---------------------------------------------------------------------------
__global__ __launch_bounds__(256) void cvt_kernel(const float* __restrict__ src, int which, int n4) {
    uint2* hi;
    uint2* lo;
    switch (which) {
        case 0: hi = (uint2*)g_w1_hi; lo = (uint2*)g_w1_lo; break;
        case 1: hi = (uint2*)g_w3_hi; lo = (uint2*)g_w3_lo; break;
        case 2: hi = (uint2*)g_w2_hi; lo = (uint2*)g_w2_lo; break;
        default: hi = (uint2*)g_x_hi;  lo = (uint2*)g_x_lo;  break;
    }
    const float4* s4 = (const float4*)src;
    int stride = gridDim.x * blockDim.x;
    for (int i = blockIdx.x * blockDim.x + threadIdx.x; i < n4; i += stride) {
        float4 f = s4[i];
        __nv_bfloat16 h0 = __float2bfloat16_rn(f.x);
        __nv_bfloat16 h1 = __float2bfloat16_rn(f.y);
        __nv_bfloat16 h2 = __float2bfloat16_rn(f.z);
        __nv_bfloat16 h3 = __float2bfloat16_rn(f.w);
        __nv_bfloat16 l0 = __float2bfloat16_rn(f.x - __bfloat162float(h0));
        __nv_bfloat16 l1 = __float2bfloat16_rn(f.y - __bfloat162float(h1));
        __nv_bfloat16 l2 = __float2bfloat16_rn(f.z - __bfloat162float(h2));
        __nv_bfloat16 l3 = __float2bfloat16_rn(f.w - __bfloat162float(h3));
        uint2 H, L;
        H.x = (uint32_t)__bfloat16_as_ushort(h0) | ((uint32_t)__bfloat16_as_ushort(h1) << 16);
        H.y = (uint32_t)__bfloat16_as_ushort(h2) | ((uint32_t)__bfloat16_as_ushort(h3) << 16);
        L.x = (uint32_t)__bfloat16_as_ushort(l0) | ((uint32_t)__bfloat16_as_ushort(l1) << 16);
        L.y = (uint32_t)__bfloat16_as_ushort(l2) | ((uint32_t)__bfloat16_as_ushort(l3) << 16);
        hi[i] = H;
        lo[i] = L;
    }
}

// ---------------------------------------------------------------------------
// GEMM1 (mma.sync bf16 3-pass): gate=X*W1^T, up=X*W3^T, h=silu(gate)*up
// Stage = 6 tiles: [Ah, Al, B1h, B1l, B3h, B3l], each 128x64 bf16 SW128.
// ---------------------------------------------------------------------------
__global__ __launch_bounds__(256, 1) void gemm1_tc() {
    const int tileId = blockIdx.y;
    if (tileId >= g_ntiles) return;
    const int e    = g_tile_e[tileId];
    const int row0 = g_tile_row0[tileId];
    const int rows = g_tile_rows[tileId];
    const int bn0  = blockIdx.x * BN;
    const int tid  = threadIdx.x;
    const int wid  = tid >> 5, lid = tid & 31;
    const int warp_m = (wid >> 2) * 64;     // 0 or 64
    const int warp_n = (wid & 3) * 32;      // 0,32,64,96

    extern __shared__ char dynsm[];
    uint32_t sb_raw = smem_u32(dynsm);
    uint32_t sb = (sb_raw + 1023u) & ~1023u;

    __shared__ int rowTok[BM];
    if (tid < BM) rowTok[tid] = g_perm[row0 + (tid < rows ? tid : rows - 1)];
    __syncthreads();

    const __nv_bfloat16* w1h = g_w1_hi + ((size_t)e * HID + bn0) * DIMD;
    const __nv_bfloat16* w1l = g_w1_lo + ((size_t)e * HID + bn0) * DIMD;
    const __nv_bfloat16* w3h = g_w3_hi + ((size_t)e * HID + bn0) * DIMD;
    const __nv_bfloat16* w3l = g_w3_lo + ((size_t)e * HID + bn0) * DIMD;

    auto load_chunk = [&](int st, int k0) {
        uint32_t base = sb + st * 6 * TILEB;
#pragma unroll
        for (int i = 0; i < 4; i++) {
            int seg = tid + i * 256;
            int r = seg >> 3, s = seg & 7;
            uint32_t so = SW(r * 128 + s * 16);
            size_t aoff = (size_t)rowTok[r] * DIMD + k0 + s * 8;
            size_t boff = (size_t)r * DIMD + k0 + s * 8;
            cpasync16(base + 0 * TILEB + so, g_x_hi + aoff);
            cpasync16(base + 1 * TILEB + so, g_x_lo + aoff);
            cpasync16(base + 2 * TILEB + so, w1h + boff);
            cpasync16(base + 3 * TILEB + so, w1l + boff);
            cpasync16(base + 4 * TILEB + so, w3h + boff);
            cpasync16(base + 5 * TILEB + so, w3l + boff);
        }
        cp_commit();
    };

    float accg[4][4][4] = {};
    float accu[4][4][4] = {};

    load_chunk(0, 0);

    // lane-invariant address pieces
    const int a_r = warp_m + (lid & 15);
    const int a_k8 = (lid >> 4) << 3;            // 0 or 8
    const int b_r = warp_n + (lid & 7) + ((lid & 16) ? 8 : 0);
    const int b_k8 = (lid & 8);                  // 0 or 8

    for (int kk = 0; kk < G1_NK; kk++) {
        const int st = kk & 1;
        if (kk + 1 < G1_NK) { load_chunk(st ^ 1, (kk + 1) * 64); cp_wait1(); }
        else cp_wait0();
        __syncthreads();

        uint32_t base = sb + st * 6 * TILEB;
#pragma unroll
        for (int k16 = 0; k16 < 64; k16 += 16) {
            uint32_t Ah[4][4], Al[4][4];
            const int acol = (k16 + a_k8) * 2;
#pragma unroll
            for (int mi = 0; mi < 4; mi++) {
                uint32_t so = SW((a_r + mi * 16) * 128 + acol);
                ldsm4(Ah[mi], base + 0 * TILEB + so);
                ldsm4(Al[mi], base + 1 * TILEB + so);
            }
            const int bcol = (k16 + b_k8) * 2;
            // gate (w1)
            {
                uint32_t Bh[2][4], Bl[2][4];
#pragma unroll
                for (int h = 0; h < 2; h++) {
                    uint32_t so = SW((b_r + h * 16) * 128 + bcol);
                    ldsm4(Bh[h], base + 2 * TILEB + so);
                    ldsm4(Bl[h], base + 3 * TILEB + so);
                }
#pragma unroll
                for (int mi = 0; mi < 4; mi++)
#pragma unroll
                    for (int nt = 0; nt < 4; nt++) {
                        const uint32_t* bh = &Bh[nt >> 1][(nt & 1) * 2];
                        const uint32_t* bl = &Bl[nt >> 1][(nt & 1) * 2];
                        mma16816(accg[mi][nt], Ah[mi], bh);
                        mma16816(accg[mi][nt], Ah[mi], bl);
                        mma16816(accg[mi][nt], Al[mi], bh);
                    }
            }
            // up (w3)
            {
                uint32_t Bh[2][4], Bl[2][4];
#pragma unroll
                for (int h = 0; h < 2; h++) {
                    uint32_t so = SW((b_r + h * 16) * 128 + bcol);
                    ldsm4(Bh[h], base + 4 * TILEB + so);
                    ldsm4(Bl[h], base + 5 * TILEB + so);
                }
#pragma unroll
                for (int mi = 0; mi < 4; mi++)
#pragma unroll
                    for (int nt = 0; nt < 4; nt++) {
                        const uint32_t* bh = &Bh[nt >> 1][(nt & 1) * 2];
                        const uint32_t* bl = &Bl[nt >> 1][(nt & 1) * 2];
                        mma16816(accu[mi][nt], Ah[mi], bh);
                        mma16816(accu[mi][nt], Ah[mi], bl);
                        mma16816(accu[mi][nt], Al[mi], bh);
                    }
            }
        }
        __syncthreads();
    }

    // Epilogue: SwiGLU; store h as bf16 hi/lo (packed col pairs)
    const int g = lid >> 2, t = lid & 3;
#pragma unroll
    for (int mi = 0; mi < 4; mi++)
#pragma unroll
        for (int nt = 0; nt < 4; nt++) {
            int col = bn0 + warp_n + nt * 8 + t * 2;
#pragma unroll
            for (int half = 0; half < 2; half++) {
                int m = warp_m + mi * 16 + g + half * 8;
                if (m < rows) {
                    float gv0 = accg[mi][nt][half * 2 + 0];
                    float gv1 = accg[mi][nt][half * 2 + 1];
                    float uv0 = accu[mi][nt][half * 2 + 0];
                    float uv1 = accu[mi][nt][half * 2 + 1];
                    float h0 = gv0 / (1.f + expf(-gv0)) * uv0;
                    float h1 = gv1 / (1.f + expf(-gv1)) * uv1;
                    __nv_bfloat16 hh0 = __float2bfloat16_rn(h0);
                    __nv_bfloat16 hh1 = __float2bfloat16_rn(h1);
                    __nv_bfloat16 hl0 = __float2bfloat16_rn(h0 - __bfloat162float(hh0));
                    __nv_bfloat16 hl1 = __float2bfloat16_rn(h1 - __bfloat162float(hh1));
                    uint32_t Hp = (uint32_t)__bfloat16_as_ushort(hh0) | ((uint32_t)__bfloat16_as_ushort(hh1) << 16);
                    uint32_t Lp = (uint32_t)__bfloat16_as_ushort(hl0) | ((uint32_t)__bfloat16_as_ushort(hl1) << 16);
                    size_t off = (size_t)(row0 + m) * HID + col;
                    *(uint32_t*)(g_h_hi + off) = Hp;
                    *(uint32_t*)(g_h_lo + off) = Lp;
                }
            }
        }
}

// ---------------------------------------------------------------------------
// GEMM2 (mma.sync bf16 3-pass): y = h * W2^T, fp32 out
// Stage = 4 tiles: [Ah, Al, Bh, Bl]
// ---------------------------------------------------------------------------
__global__ __launch_bounds__(256, 1) void gemm2_tc() {
    const int tileId = blockIdx.y;
    if (tileId >= g_ntiles) return;
    const int e    = g_tile_e[tileId];
    const int row0 = g_tile_row0[tileId];
    const int rows = g_tile_rows[tileId];
    const int bn0  = blockIdx.x * BN;
    const int tid  = threadIdx.x;
    const int wid  = tid >> 5, lid = tid & 31;
    const int warp_m = (wid >> 2) * 64;
    const int warp_n = (wid & 3) * 32;

    extern __shared__ char dynsm[];
    uint32_t sb_raw = smem_u32(dynsm);
    uint32_t sb = (sb_raw + 1023u) & ~1023u;

    const __nv_bfloat16* bh_g = g_w2_hi + ((size_t)e * DIMD + bn0) * HID;
    const __nv_bfloat16* bl_g = g_w2_lo + ((size_t)e * DIMD + bn0) * HID;

    auto load_chunk = [&](int st, int k0) {
        uint32_t base = sb + st * 4 * TILEB;
#pragma unroll
        for (int i = 0; i < 4; i++) {
            int seg = tid + i * 256;
            int r = seg >> 3, s = seg & 7;
            int ar = r < rows ? r : rows - 1;
            uint32_t so = SW(r * 128 + s * 16);
            size_t aoff = (size_t)(row0 + ar) * HID + k0 + s * 8;
            size_t boff = (size_t)r * HID + k0 + s * 8;
            cpasync16(base + 0 * TILEB + so, g_h_hi + aoff);
            cpasync16(base + 1 * TILEB + so, g_h_lo + aoff);
            cpasync16(base + 2 * TILEB + so, bh_g + boff);
            cpasync16(base + 3 * TILEB + so, bl_g + boff);
        }
        cp_commit();
    };

    float acc[4][4][4] = {};

    load_chunk(0, 0);

    const int a_r = warp_m + (lid & 15);
    const int a_k8 = (lid >> 4) << 3;
    const int b_r = warp_n + (lid & 7) + ((lid & 16) ? 8 : 0);
    const int b_k8 = (lid & 8);

    for (int kk = 0; kk < G2_NK; kk++) {
        const int st = kk & 1;
        if (kk + 1 < G2_NK) { load_chunk(st ^ 1, (kk + 1) * 64); cp_wait1(); }
        else cp_wait0();
        __syncthreads();

        uint32_t base = sb + st * 4 * TILEB;
#pragma unroll
        for (int k16 = 0; k16 < 64; k16 += 16) {
            uint32_t Ah[4][4], Al[4][4];
            const int acol = (k16 + a_k8) * 2;
#pragma unroll
            for (int mi = 0; mi < 4; mi++) {
                uint32_t so = SW((a_r + mi * 16) * 128 + acol);
                ldsm4(Ah[mi], base + 0 * TILEB + so);
                ldsm4(Al[mi], base + 1 * TILEB + so);
            }
            const int bcol = (k16 + b_k8) * 2;
            uint32_t Bh[2][4], Bl[2][4];
#pragma unroll
            for (int h = 0; h < 2; h++) {
                uint32_t so = SW((b_r + h * 16) * 128 + bcol);
                ldsm4(Bh[h], base + 2 * TILEB + so);
                ldsm4(Bl[h], base + 3 * TILEB + so);
            }
#pragma unroll
            for (int mi = 0; mi < 4; mi++)
#pragma unroll
                for (int nt = 0; nt < 4; nt++) {
                    const uint32_t* bh = &Bh[nt >> 1][(nt & 1) * 2];
                    const uint32_t* bl = &Bl[nt >> 1][(nt & 1) * 2];
                    mma16816(acc[mi][nt], Ah[mi], bh);
                    mma16816(acc[mi][nt], Ah[mi], bl);
                    mma16816(acc[mi][nt], Al[mi], bh);
                }
        }
        __syncthreads();
    }

    const int g = lid >> 2, t = lid & 3;
#pragma unroll
    for (int mi = 0; mi < 4; mi++)
#pragma unroll
        for (int nt = 0; nt < 4; nt++) {
            int col = bn0 + warp_n + nt * 8 + t * 2;
#pragma unroll
            for (int half = 0; half < 2; half++) {
                int m = warp_m + mi * 16 + g + half * 8;
                if (m < rows) {
                    float2 v;
                    v.x = acc[mi][nt][half * 2 + 0];
                    v.y = acc[mi][nt][half * 2 + 1];
                    *(float2*)(g_y + (size_t)(row0 + m) * DIMD + col) = v;
                }
            }
        }
}

// ---------------------------------------------------------------------------
// RMSNorm + norm_w + scatter to token order
// ---------------------------------------------------------------------------
__global__ __launch_bounds__(256) void norm_kernel(
    const float* __restrict__ norm_w,
    const int* __restrict__ ids,
    float* __restrict__ out)
{
    const int i   = blockIdx.x;
    const int tid = threadIdx.x;
    const int tok = g_perm[i];
    const int e   = ids[tok];
    const float* yr = g_y + (size_t)i * DIMD;

    float s = 0.f;
#pragma unroll
    for (int j = tid * 4; j < DIMD; j += 256 * 4) {
        float4 v = *(const float4*)(yr + j);
        s += v.x * v.x + v.y * v.y + v.z * v.z + v.w * v.w;
    }
#pragma unroll
    for (int o = 16; o; o >>= 1) s += __shfl_xor_sync(0xFFFFFFFFu, s, o);

    __shared__ float ws[8];
    __shared__ float stot;
    if ((tid & 31) == 0) ws[tid >> 5] = s;
    __syncthreads();
    if (tid == 0) {
        float t = 0.f;
#pragma unroll
        for (int w = 0; w < 8; w++) t += ws[w];
        stot = t;
    }
    __syncthreads();

    const float scale = rsqrtf(stot * (1.0f / DIMD) + EPSV);
    const float* nw = norm_w + (size_t)e * DIMD;
    float* op = out + (size_t)tok * DIMD;
#pragma unroll
    for (int j = tid * 4; j < DIMD; j += 256 * 4) {
        float4 v = *(const float4*)(yr + j);
        float4 w = *(const float4*)(nw + j);
        float4 r;
        r.x = v.x * scale * w.x;
        r.y = v.y * scale * w.y;
        r.z = v.z * scale * w.z;
        r.w = v.w * scale * w.w;
        *(float4*)(op + j) = r;
    }
}

// ---------------------------------------------------------------------------
extern "C" void kernel_launch(void* const* d_in, const int* in_sizes, int n_in,
                              void* d_out, int out_size) {
    const float* x      = (const float*)d_in[0];
    const float* w1     = (const float*)d_in[1];
    const float* w2     = (const float*)d_in[2];
    const float* w3     = (const float*)d_in[3];
    const float* norm_w = (const float*)d_in[4];
    const int*   ids    = (const int*)d_in[5];
    float* out = (float*)d_out;

    const int SMEM1 = 2 * 6 * TILEB + 1024;  // 197632
    const int SMEM2 = 2 * 4 * TILEB + 1024;  // 132096
    cudaFuncSetAttribute(gemm1_tc, cudaFuncAttributeMaxDynamicSharedMemorySize, SMEM1);
    cudaFuncSetAttribute(gemm2_tc, cudaFuncAttributeMaxDynamicSharedMemorySize, SMEM2);

    route_kernel<<<1, 256>>>(ids);

    const int wN4 = (NEXP * HID * DIMD) / 4;
    const int xN4 = (NTOK * DIMD) / 4;
    cvt_kernel<<<1184, 256>>>(w1, 0, wN4);
    cvt_kernel<<<1184, 256>>>(w3, 1, wN4);
    cvt_kernel<<<1184, 256>>>(w2, 2, wN4);
    cvt_kernel<<<1184, 256>>>(x, 3, xN4);

    dim3 g1(HID / BN, MAX_TILES);
    gemm1_tc<<<g1, 256, SMEM1>>>();

    dim3 g2(DIMD / BN, MAX_TILES);
    gemm2_tc<<<g2, 256, SMEM2>>>();

    norm_kernel<<<NTOK, 256>>>(norm_w, ids, out);
}

// round 4
// speedup vs baseline: 3.7111x; 1.0008x over previous
#include <cuda_runtime.h>
#include <cuda_bf16.h>
#include <math.h>
#include <stdint.h>

// ---------------------------------------------------------------------------
// Problem constants
// ---------------------------------------------------------------------------
#define DIMD 2048
#define HID  3840
#define NTOK 8192
#define NEXP 4
#define EPSV 1e-5f
#define BM 128
#define BN 128
#define MAX_TILES (NTOK / BM + NEXP)

#define G1_NK (DIMD / 64)   // 32 K-chunks of 64
#define G2_NK (HID / 64)    // 60 K-chunks of 64
#define TILEB 16384         // one 128x64 bf16 tile = 16KB (128B rows, SW128)

// SW128 swizzle (Swizzle<3,4,3>) on byte offsets within a tile
#define SW(o) ((o) ^ (((o) >> 3) & 0x70))

// ---------------------------------------------------------------------------
// Scratch (device globals: allocation-free)
// ---------------------------------------------------------------------------
__device__ __nv_bfloat16 g_x_hi[(size_t)NTOK * DIMD];
__device__ __nv_bfloat16 g_x_lo[(size_t)NTOK * DIMD];
__device__ __nv_bfloat16 g_w1_hi[(size_t)NEXP * HID * DIMD];
__device__ __nv_bfloat16 g_w1_lo[(size_t)NEXP * HID * DIMD];
__device__ __nv_bfloat16 g_w3_hi[(size_t)NEXP * HID * DIMD];
__device__ __nv_bfloat16 g_w3_lo[(size_t)NEXP * HID * DIMD];
__device__ __nv_bfloat16 g_w2_hi[(size_t)NEXP * DIMD * HID];
__device__ __nv_bfloat16 g_w2_lo[(size_t)NEXP * DIMD * HID];
__device__ __nv_bfloat16 g_h_hi[(size_t)NTOK * HID];
__device__ __nv_bfloat16 g_h_lo[(size_t)NTOK * HID];
__device__ float g_y[(size_t)NTOK * DIMD];
__device__ int   g_perm[NTOK];
__device__ int   g_tile_e[MAX_TILES];
__device__ int   g_tile_row0[MAX_TILES];
__device__ int   g_tile_rows[MAX_TILES];
__device__ int   g_ntiles;

// ---------------------------------------------------------------------------
// PTX helpers (sm_80-baseline: legal at plain compute_103)
// ---------------------------------------------------------------------------
__device__ __forceinline__ uint32_t smem_u32(const void* p) {
    uint32_t a;
    asm("{ .reg .u64 t; cvta.to.shared.u64 t, %1; cvt.u32.u64 %0, t; }" : "=r"(a) : "l"(p));
    return a;
}
__device__ __forceinline__ void cpasync16(uint32_t dst, const void* src) {
    asm volatile("cp.async.cg.shared.global [%0], [%1], 16;" :: "r"(dst), "l"(src) : "memory");
}
__device__ __forceinline__ void cp_commit() {
    asm volatile("cp.async.commit_group;" ::: "memory");
}
__device__ __forceinline__ void cp_wait1() {
    asm volatile("cp.async.wait_group 1;" ::: "memory");
}
__device__ __forceinline__ void cp_wait0() {
    asm volatile("cp.async.wait_group 0;" ::: "memory");
}
__device__ __forceinline__ void ldsm4(uint32_t* r, uint32_t addr) {
    asm volatile("ldmatrix.sync.aligned.m8n8.x4.shared.b16 {%0,%1,%2,%3}, [%4];"
                 : "=r"(r[0]), "=r"(r[1]), "=r"(r[2]), "=r"(r[3]) : "r"(addr));
}
__device__ __forceinline__ void mma16816(float* d, const uint32_t* a, const uint32_t* b) {
    asm volatile("mma.sync.aligned.m16n8k16.row.col.f32.bf16.bf16.f32 "
                 "{%0,%1,%2,%3}, {%4,%5,%6,%7}, {%8,%9}, {%0,%1,%2,%3};"
                 : "+f"(d[0]), "+f"(d[1]), "+f"(d[2]), "+f"(d[3])
                 : "r"(a[0]), "r"(a[1]), "r"(a[2]), "r"(a[3]), "r"(b[0]), "r"(b[1]));
}

// ---------------------------------------------------------------------------
// Routing
// ---------------------------------------------------------------------------
__global__ void route_kernel(const int* __restrict__ ids) {
    __shared__ int cnt[NEXP];
    __shared__ int cur[NEXP];
    int tid = threadIdx.x;
    if (tid < NEXP) cnt[tid] = 0;
    __syncthreads();
    for (int t = tid; t < NTOK; t += blockDim.x) atomicAdd(&cnt[ids[t]], 1);
    __syncthreads();
    if (tid == 0) {
        int o = 0, nt = 0;
        for (int e = 0; e < NEXP; e++) {
            cur[e] = o;
            int c = cnt[e];
            for (int r = 0; r < c; r += BM) {
                g_tile_e[nt] = e;
                g_tile_row0[nt] = o + r;
                g_tile_rows[nt] = (c - r) < BM ? (c - r) : BM;
                nt++;
            }
            o += c;
        }
        g_ntiles = nt;
    }
    __syncthreads();
    for (int t = tid; t < NTOK; t += blockDim.x) {
        int p = atomicAdd(&cur[ids[t]], 1);
        g_perm[p] = t;
    }
}

// ---------------------------------------------------------------------------
// fp32 -> bf16 hi/lo split. which: 0=w1, 1=w3, 2=w2, 3=x
// ---------------------------------------------------------------------------
__global__ __launch_bounds__(256) void cvt_kernel(const float* __restrict__ src, int which, int n4) {
    uint2* hi;
    uint2* lo;
    switch (which) {
        case 0: hi = (uint2*)g_w1_hi; lo = (uint2*)g_w1_lo; break;
        case 1: hi = (uint2*)g_w3_hi; lo = (uint2*)g_w3_lo; break;
        case 2: hi = (uint2*)g_w2_hi; lo = (uint2*)g_w2_lo; break;
        default: hi = (uint2*)g_x_hi;  lo = (uint2*)g_x_lo;  break;
    }
    const float4* s4 = (const float4*)src;
    int stride = gridDim.x * blockDim.x;
    for (int i = blockIdx.x * blockDim.x + threadIdx.x; i < n4; i += stride) {
        float4 f = s4[i];
        __nv_bfloat16 h0 = __float2bfloat16_rn(f.x);
        __nv_bfloat16 h1 = __float2bfloat16_rn(f.y);
        __nv_bfloat16 h2 = __float2bfloat16_rn(f.z);
        __nv_bfloat16 h3 = __float2bfloat16_rn(f.w);
        __nv_bfloat16 l0 = __float2bfloat16_rn(f.x - __bfloat162float(h0));
        __nv_bfloat16 l1 = __float2bfloat16_rn(f.y - __bfloat162float(h1));
        __nv_bfloat16 l2 = __float2bfloat16_rn(f.z - __bfloat162float(h2));
        __nv_bfloat16 l3 = __float2bfloat16_rn(f.w - __bfloat162float(h3));
        uint2 H, L;
        H.x = (uint32_t)__bfloat16_as_ushort(h0) | ((uint32_t)__bfloat16_as_ushort(h1) << 16);
        H.y = (uint32_t)__bfloat16_as_ushort(h2) | ((uint32_t)__bfloat16_as_ushort(h3) << 16);
        L.x = (uint32_t)__bfloat16_as_ushort(l0) | ((uint32_t)__bfloat16_as_ushort(l1) << 16);
        L.y = (uint32_t)__bfloat16_as_ushort(l2) | ((uint32_t)__bfloat16_as_ushort(l3) << 16);
        hi[i] = H;
        lo[i] = L;
    }
}

// ---------------------------------------------------------------------------
// GEMM1 (mma.sync bf16 3-pass): gate=X*W1^T, up=X*W3^T, h=silu(gate)*up
// Grid: x = m-tile (fast-varying -> wave shares one weight tile via L2),
//       y = bn group.
// ---------------------------------------------------------------------------
__global__ __launch_bounds__(256, 1) void gemm1_tc() {
    const int tileId = blockIdx.x;
    if (tileId >= g_ntiles) return;
    const int e    = g_tile_e[tileId];
    const int row0 = g_tile_row0[tileId];
    const int rows = g_tile_rows[tileId];
    const int bn0  = blockIdx.y * BN;
    const int tid  = threadIdx.x;
    const int wid  = tid >> 5, lid = tid & 31;
    const int warp_m = (wid >> 2) * 64;     // 0 or 64
    const int warp_n = (wid & 3) * 32;      // 0,32,64,96

    extern __shared__ char dynsm[];
    uint32_t sb_raw = smem_u32(dynsm);
    uint32_t sb = (sb_raw + 1023u) & ~1023u;

    __shared__ int rowTok[BM];
    if (tid < BM) rowTok[tid] = g_perm[row0 + (tid < rows ? tid : rows - 1)];
    __syncthreads();

    const __nv_bfloat16* w1h = g_w1_hi + ((size_t)e * HID + bn0) * DIMD;
    const __nv_bfloat16* w1l = g_w1_lo + ((size_t)e * HID + bn0) * DIMD;
    const __nv_bfloat16* w3h = g_w3_hi + ((size_t)e * HID + bn0) * DIMD;
    const __nv_bfloat16* w3l = g_w3_lo + ((size_t)e * HID + bn0) * DIMD;

    auto load_chunk = [&](int st, int k0) {
        uint32_t base = sb + st * 6 * TILEB;
#pragma unroll
        for (int i = 0; i < 4; i++) {
            int seg = tid + i * 256;
            int r = seg >> 3, s = seg & 7;
            uint32_t so = SW(r * 128 + s * 16);
            size_t aoff = (size_t)rowTok[r] * DIMD + k0 + s * 8;
            size_t boff = (size_t)r * DIMD + k0 + s * 8;
            cpasync16(base + 0 * TILEB + so, g_x_hi + aoff);
            cpasync16(base + 1 * TILEB + so, g_x_lo + aoff);
            cpasync16(base + 2 * TILEB + so, w1h + boff);
            cpasync16(base + 3 * TILEB + so, w1l + boff);
            cpasync16(base + 4 * TILEB + so, w3h + boff);
            cpasync16(base + 5 * TILEB + so, w3l + boff);
        }
        cp_commit();
    };

    float accg[4][4][4] = {};
    float accu[4][4][4] = {};

    load_chunk(0, 0);

    const int a_r = warp_m + (lid & 15);
    const int a_k8 = (lid >> 4) << 3;            // 0 or 8
    const int b_r = warp_n + (lid & 7) + ((lid & 16) ? 8 : 0);
    const int b_k8 = (lid & 8);                  // 0 or 8

    for (int kk = 0; kk < G1_NK; kk++) {
        const int st = kk & 1;
        if (kk + 1 < G1_NK) { load_chunk(st ^ 1, (kk + 1) * 64); cp_wait1(); }
        else cp_wait0();
        __syncthreads();

        uint32_t base = sb + st * 6 * TILEB;
#pragma unroll
        for (int k16 = 0; k16 < 64; k16 += 16) {
            uint32_t Ah[4][4], Al[4][4];
            const int acol = (k16 + a_k8) * 2;
#pragma unroll
            for (int mi = 0; mi < 4; mi++) {
                uint32_t so = SW((a_r + mi * 16) * 128 + acol);
                ldsm4(Ah[mi], base + 0 * TILEB + so);
                ldsm4(Al[mi], base + 1 * TILEB + so);
            }
            const int bcol = (k16 + b_k8) * 2;
            // gate (w1)
            {
                uint32_t Bh[2][4], Bl[2][4];
#pragma unroll
                for (int h = 0; h < 2; h++) {
                    uint32_t so = SW((b_r + h * 16) * 128 + bcol);
                    ldsm4(Bh[h], base + 2 * TILEB + so);
                    ldsm4(Bl[h], base + 3 * TILEB + so);
                }
#pragma unroll
                for (int mi = 0; mi < 4; mi++)
#pragma unroll
                    for (int nt = 0; nt < 4; nt++) {
                        const uint32_t* bh = &Bh[nt >> 1][(nt & 1) * 2];
                        const uint32_t* bl = &Bl[nt >> 1][(nt & 1) * 2];
                        mma16816(accg[mi][nt], Ah[mi], bh);
                        mma16816(accg[mi][nt], Ah[mi], bl);
                        mma16816(accg[mi][nt], Al[mi], bh);
                    }
            }
            // up (w3)
            {
                uint32_t Bh[2][4], Bl[2][4];
#pragma unroll
                for (int h = 0; h < 2; h++) {
                    uint32_t so = SW((b_r + h * 16) * 128 + bcol);
                    ldsm4(Bh[h], base + 4 * TILEB + so);
                    ldsm4(Bl[h], base + 5 * TILEB + so);
                }
#pragma unroll
                for (int mi = 0; mi < 4; mi++)
#pragma unroll
                    for (int nt = 0; nt < 4; nt++) {
                        const uint32_t* bh = &Bh[nt >> 1][(nt & 1) * 2];
                        const uint32_t* bl = &Bl[nt >> 1][(nt & 1) * 2];
                        mma16816(accu[mi][nt], Ah[mi], bh);
                        mma16816(accu[mi][nt], Ah[mi], bl);
                        mma16816(accu[mi][nt], Al[mi], bh);
                    }
            }
        }
        __syncthreads();
    }

    // Epilogue: SwiGLU; store h as bf16 hi/lo (packed col pairs)
    const int g = lid >> 2, t = lid & 3;
#pragma unroll
    for (int mi = 0; mi < 4; mi++)
#pragma unroll
        for (int nt = 0; nt < 4; nt++) {
            int col = bn0 + warp_n + nt * 8 + t * 2;
#pragma unroll
            for (int half = 0; half < 2; half++) {
                int m = warp_m + mi * 16 + g + half * 8;
                if (m < rows) {
                    float gv0 = accg[mi][nt][half * 2 + 0];
                    float gv1 = accg[mi][nt][half * 2 + 1];
                    float uv0 = accu[mi][nt][half * 2 + 0];
                    float uv1 = accu[mi][nt][half * 2 + 1];
                    float h0 = gv0 / (1.f + expf(-gv0)) * uv0;
                    float h1 = gv1 / (1.f + expf(-gv1)) * uv1;
                    __nv_bfloat16 hh0 = __float2bfloat16_rn(h0);
                    __nv_bfloat16 hh1 = __float2bfloat16_rn(h1);
                    __nv_bfloat16 hl0 = __float2bfloat16_rn(h0 - __bfloat162float(hh0));
                    __nv_bfloat16 hl1 = __float2bfloat16_rn(h1 - __bfloat162float(hh1));
                    uint32_t Hp = (uint32_t)__bfloat16_as_ushort(hh0) | ((uint32_t)__bfloat16_as_ushort(hh1) << 16);
                    uint32_t Lp = (uint32_t)__bfloat16_as_ushort(hl0) | ((uint32_t)__bfloat16_as_ushort(hl1) << 16);
                    size_t off = (size_t)(row0 + m) * HID + col;
                    *(uint32_t*)(g_h_hi + off) = Hp;
                    *(uint32_t*)(g_h_lo + off) = Lp;
                }
            }
        }
}

// ---------------------------------------------------------------------------
// GEMM2 (mma.sync bf16 3-pass): y = h * W2^T, fp32 out
// Grid: x = m-tile, y = bn group (same rationale).
// ---------------------------------------------------------------------------
__global__ __launch_bounds__(256, 1) void gemm2_tc() {
    const int tileId = blockIdx.x;
    if (tileId >= g_ntiles) return;
    const int e    = g_tile_e[tileId];
    const int row0 = g_tile_row0[tileId];
    const int rows = g_tile_rows[tileId];
    const int bn0  = blockIdx.y * BN;
    const int tid  = threadIdx.x;
    const int wid  = tid >> 5, lid = tid & 31;
    const int warp_m = (wid >> 2) * 64;
    const int warp_n = (wid & 3) * 32;

    extern __shared__ char dynsm[];
    uint32_t sb_raw = smem_u32(dynsm);
    uint32_t sb = (sb_raw + 1023u) & ~1023u;

    const __nv_bfloat16* bh_g = g_w2_hi + ((size_t)e * DIMD + bn0) * HID;
    const __nv_bfloat16* bl_g = g_w2_lo + ((size_t)e * DIMD + bn0) * HID;

    auto load_chunk = [&](int st, int k0) {
        uint32_t base = sb + st * 4 * TILEB;
#pragma unroll
        for (int i = 0; i < 4; i++) {
            int seg = tid + i * 256;
            int r = seg >> 3, s = seg & 7;
            int ar = r < rows ? r : rows - 1;
            uint32_t so = SW(r * 128 + s * 16);
            size_t aoff = (size_t)(row0 + ar) * HID + k0 + s * 8;
            size_t boff = (size_t)r * HID + k0 + s * 8;
            cpasync16(base + 0 * TILEB + so, g_h_hi + aoff);
            cpasync16(base + 1 * TILEB + so, g_h_lo + aoff);
            cpasync16(base + 2 * TILEB + so, bh_g + boff);
            cpasync16(base + 3 * TILEB + so, bl_g + boff);
        }
        cp_commit();
    };

    float acc[4][4][4] = {};

    load_chunk(0, 0);

    const int a_r = warp_m + (lid & 15);
    const int a_k8 = (lid >> 4) << 3;
    const int b_r = warp_n + (lid & 7) + ((lid & 16) ? 8 : 0);
    const int b_k8 = (lid & 8);

    for (int kk = 0; kk < G2_NK; kk++) {
        const int st = kk & 1;
        if (kk + 1 < G2_NK) { load_chunk(st ^ 1, (kk + 1) * 64); cp_wait1(); }
        else cp_wait0();
        __syncthreads();

        uint32_t base = sb + st * 4 * TILEB;
#pragma unroll
        for (int k16 = 0; k16 < 64; k16 += 16) {
            uint32_t Ah[4][4], Al[4][4];
            const int acol = (k16 + a_k8) * 2;
#pragma unroll
            for (int mi = 0; mi < 4; mi++) {
                uint32_t so = SW((a_r + mi * 16) * 128 + acol);
                ldsm4(Ah[mi], base + 0 * TILEB + so);
                ldsm4(Al[mi], base + 1 * TILEB + so);
            }
            const int bcol = (k16 + b_k8) * 2;
            uint32_t Bh[2][4], Bl[2][4];
#pragma unroll
            for (int h = 0; h < 2; h++) {
                uint32_t so = SW((b_r + h * 16) * 128 + bcol);
                ldsm4(Bh[h], base + 2 * TILEB + so);
                ldsm4(Bl[h], base + 3 * TILEB + so);
            }
#pragma unroll
            for (int mi = 0; mi < 4; mi++)
#pragma unroll
                for (int nt = 0; nt < 4; nt++) {
                    const uint32_t* bh = &Bh[nt >> 1][(nt & 1) * 2];
                    const uint32_t* bl = &Bl[nt >> 1][(nt & 1) * 2];
                    mma16816(acc[mi][nt], Ah[mi], bh);
                    mma16816(acc[mi][nt], Ah[mi], bl);
                    mma16816(acc[mi][nt], Al[mi], bh);
                }
        }
        __syncthreads();
    }

    const int g = lid >> 2, t = lid & 3;
#pragma unroll
    for (int mi = 0; mi < 4; mi++)
#pragma unroll
        for (int nt = 0; nt < 4; nt++) {
            int col = bn0 + warp_n + nt * 8 + t * 2;
#pragma unroll
            for (int half = 0; half < 2; half++) {
                int m = warp_m + mi * 16 + g + half * 8;
                if (m < rows) {
                    float2 v;
                    v.x = acc[mi][nt][half * 2 + 0];
                    v.y = acc[mi][nt][half * 2 + 1];
                    *(float2*)(g_y + (size_t)(row0 + m) * DIMD + col) = v;
                }
            }
        }
}

// ---------------------------------------------------------------------------
// RMSNorm + norm_w + scatter to token order
// ---------------------------------------------------------------------------
__global__ __launch_bounds__(256) void norm_kernel(
    const float* __restrict__ norm_w,
    const int* __restrict__ ids,
    float* __restrict__ out)
{
    const int i   = blockIdx.x;
    const int tid = threadIdx.x;
    const int tok = g_perm[i];
    const int e   = ids[tok];
    const float* yr = g_y + (size_t)i * DIMD;

    float s = 0.f;
#pragma unroll
    for (int j = tid * 4; j < DIMD; j += 256 * 4) {
        float4 v = *(const float4*)(yr + j);
        s += v.x * v.x + v.y * v.y + v.z * v.z + v.w * v.w;
    }
#pragma unroll
    for (int o = 16; o; o >>= 1) s += __shfl_xor_sync(0xFFFFFFFFu, s, o);

    __shared__ float ws[8];
    __shared__ float stot;
    if ((tid & 31) == 0) ws[tid >> 5] = s;
    __syncthreads();
    if (tid == 0) {
        float t = 0.f;
#pragma unroll
        for (int w = 0; w < 8; w++) t += ws[w];
        stot = t;
    }
    __syncthreads();

    const float scale = rsqrtf(stot * (1.0f / DIMD) + EPSV);
    const float* nw = norm_w + (size_t)e * DIMD;
    float* op = out + (size_t)tok * DIMD;
#pragma unroll
    for (int j = tid * 4; j < DIMD; j += 256 * 4) {
        float4 v = *(const float4*)(yr + j);
        float4 w = *(const float4*)(nw + j);
        float4 r;
        r.x = v.x * scale * w.x;
        r.y = v.y * scale * w.y;
        r.z = v.z * scale * w.z;
        r.w = v.w * scale * w.w;
        *(float4*)(op + j) = r;
    }
}

// ---------------------------------------------------------------------------
extern "C" void kernel_launch(void* const* d_in, const int* in_sizes, int n_in,
                              void* d_out, int out_size) {
    const float* x      = (const float*)d_in[0];
    const float* w1     = (const float*)d_in[1];
    const float* w2     = (const float*)d_in[2];
    const float* w3     = (const float*)d_in[3];
    const float* norm_w = (const float*)d_in[4];
    const int*   ids    = (const int*)d_in[5];
    float* out = (float*)d_out;

    const int SMEM1 = 2 * 6 * TILEB + 1024;  // 197632
    const int SMEM2 = 2 * 4 * TILEB + 1024;  // 132096
    cudaFuncSetAttribute(gemm1_tc, cudaFuncAttributeMaxDynamicSharedMemorySize, SMEM1);
    cudaFuncSetAttribute(gemm2_tc, cudaFuncAttributeMaxDynamicSharedMemorySize, SMEM2);

    route_kernel<<<1, 256>>>(ids);

    const int wN4 = (NEXP * HID * DIMD) / 4;
    const int xN4 = (NTOK * DIMD) / 4;
    cvt_kernel<<<1184, 256>>>(w1, 0, wN4);
    cvt_kernel<<<1184, 256>>>(w3, 1, wN4);
    cvt_kernel<<<1184, 256>>>(w2, 2, wN4);
    cvt_kernel<<<1184, 256>>>(x, 3, xN4);

    dim3 g1(MAX_TILES, HID / BN);   // x = m-tile (fast) -> wave-level weight reuse in L2
    gemm1_tc<<<g1, 256, SMEM1>>>();

    dim3 g2(MAX_TILES, DIMD / BN);
    gemm2_tc<<<g2, 256, SMEM2>>>();

    norm_kernel<<<NTOK, 256>>>(norm_w, ids, out);
}

// round 5
// speedup vs baseline: 5.2476x; 1.4140x over previous
#include <cuda_runtime.h>
#include <cuda_fp16.h>
#include <math.h>
#include <stdint.h>

// ---------------------------------------------------------------------------
// Problem constants
// ---------------------------------------------------------------------------
#define DIMD 2048
#define HID  3840
#define NTOK 8192
#define NEXP 4
#define EPSV 1e-5f
#define BM 128
#define BN 128
#define MAX_TILES (NTOK / BM + NEXP)

#define G1_NK (DIMD / 64)   // 32 K-chunks of 64
#define G2_NK (HID / 64)    // 60 K-chunks of 64
#define TILEB 16384         // one 128x64 fp16 tile = 16KB (128B rows, SW128)

// SW128 swizzle (Swizzle<3,4,3>) on byte offsets within a tile
#define SW(o) ((o) ^ (((o) >> 3) & 0x70))

// ---------------------------------------------------------------------------
// Scratch (device globals: allocation-free)
// fp16 2-pass scheme: activations split hi/lo, weights single fp16 (rn).
// ---------------------------------------------------------------------------
__device__ __half g_x_hi[(size_t)NTOK * DIMD];
__device__ __half g_x_lo[(size_t)NTOK * DIMD];
__device__ __half g_w1[(size_t)NEXP * HID * DIMD];
__device__ __half g_w3[(size_t)NEXP * HID * DIMD];
__device__ __half g_w2[(size_t)NEXP * DIMD * HID];
__device__ __half g_h_hi[(size_t)NTOK * HID];
__device__ __half g_h_lo[(size_t)NTOK * HID];
__device__ float g_y[(size_t)NTOK * DIMD];
__device__ int   g_perm[NTOK];
__device__ int   g_tile_e[MAX_TILES];
__device__ int   g_tile_row0[MAX_TILES];
__device__ int   g_tile_rows[MAX_TILES];
__device__ int   g_ntiles;

// ---------------------------------------------------------------------------
// PTX helpers (sm_80-baseline: legal at plain compute_103)
// ---------------------------------------------------------------------------
__device__ __forceinline__ uint32_t smem_u32(const void* p) {
    uint32_t a;
    asm("{ .reg .u64 t; cvta.to.shared.u64 t, %1; cvt.u32.u64 %0, t; }" : "=r"(a) : "l"(p));
    return a;
}
__device__ __forceinline__ void cpasync16(uint32_t dst, const void* src) {
    asm volatile("cp.async.cg.shared.global [%0], [%1], 16;" :: "r"(dst), "l"(src) : "memory");
}
__device__ __forceinline__ void cp_commit() {
    asm volatile("cp.async.commit_group;" ::: "memory");
}
__device__ __forceinline__ void cp_wait1() {
    asm volatile("cp.async.wait_group 1;" ::: "memory");
}
__device__ __forceinline__ void cp_wait0() {
    asm volatile("cp.async.wait_group 0;" ::: "memory");
}
__device__ __forceinline__ void ldsm4(uint32_t* r, uint32_t addr) {
    asm volatile("ldmatrix.sync.aligned.m8n8.x4.shared.b16 {%0,%1,%2,%3}, [%4];"
                 : "=r"(r[0]), "=r"(r[1]), "=r"(r[2]), "=r"(r[3]) : "r"(addr));
}
__device__ __forceinline__ void mma16816(float* d, const uint32_t* a, const uint32_t* b) {
    asm volatile("mma.sync.aligned.m16n8k16.row.col.f32.f16.f16.f32 "
                 "{%0,%1,%2,%3}, {%4,%5,%6,%7}, {%8,%9}, {%0,%1,%2,%3};"
                 : "+f"(d[0]), "+f"(d[1]), "+f"(d[2]), "+f"(d[3])
                 : "r"(a[0]), "r"(a[1]), "r"(a[2]), "r"(a[3]), "r"(b[0]), "r"(b[1]));
}

// ---------------------------------------------------------------------------
// Routing
// ---------------------------------------------------------------------------
__global__ void route_kernel(const int* __restrict__ ids) {
    __shared__ int cnt[NEXP];
    __shared__ int cur[NEXP];
    int tid = threadIdx.x;
    if (tid < NEXP) cnt[tid] = 0;
    __syncthreads();
    for (int t = tid; t < NTOK; t += blockDim.x) atomicAdd(&cnt[ids[t]], 1);
    __syncthreads();
    if (tid == 0) {
        int o = 0, nt = 0;
        for (int e = 0; e < NEXP; e++) {
            cur[e] = o;
            int c = cnt[e];
            for (int r = 0; r < c; r += BM) {
                g_tile_e[nt] = e;
                g_tile_row0[nt] = o + r;
                g_tile_rows[nt] = (c - r) < BM ? (c - r) : BM;
                nt++;
            }
            o += c;
        }
        g_ntiles = nt;
    }
    __syncthreads();
    for (int t = tid; t < NTOK; t += blockDim.x) {
        int p = atomicAdd(&cur[ids[t]], 1);
        g_perm[p] = t;
    }
}

// ---------------------------------------------------------------------------
// fp32 -> fp16 (weights, single). which: 0=w1, 1=w3, 2=w2
// ---------------------------------------------------------------------------
__global__ __launch_bounds__(256) void cvt_w_kernel(const float* __restrict__ src, int which, int n4) {
    uint2* dst;
    switch (which) {
        case 0: dst = (uint2*)g_w1; break;
        case 1: dst = (uint2*)g_w3; break;
        default: dst = (uint2*)g_w2; break;
    }
    const float4* s4 = (const float4*)src;
    int stride = gridDim.x * blockDim.x;
    for (int i = blockIdx.x * blockDim.x + threadIdx.x; i < n4; i += stride) {
        float4 f = s4[i];
        __half h0 = __float2half_rn(f.x);
        __half h1 = __float2half_rn(f.y);
        __half h2 = __float2half_rn(f.z);
        __half h3 = __float2half_rn(f.w);
        uint2 H;
        H.x = (uint32_t)__half_as_ushort(h0) | ((uint32_t)__half_as_ushort(h1) << 16);
        H.y = (uint32_t)__half_as_ushort(h2) | ((uint32_t)__half_as_ushort(h3) << 16);
        dst[i] = H;
    }
}

// ---------------------------------------------------------------------------
// fp32 -> fp16 hi/lo split (x activations)
// ---------------------------------------------------------------------------
__global__ __launch_bounds__(256) void cvt_x_kernel(const float* __restrict__ src, int n4) {
    uint2* hi = (uint2*)g_x_hi;
    uint2* lo = (uint2*)g_x_lo;
    const float4* s4 = (const float4*)src;
    int stride = gridDim.x * blockDim.x;
    for (int i = blockIdx.x * blockDim.x + threadIdx.x; i < n4; i += stride) {
        float4 f = s4[i];
        __half h0 = __float2half_rn(f.x);
        __half h1 = __float2half_rn(f.y);
        __half h2 = __float2half_rn(f.z);
        __half h3 = __float2half_rn(f.w);
        __half l0 = __float2half_rn(f.x - __half2float(h0));
        __half l1 = __float2half_rn(f.y - __half2float(h1));
        __half l2 = __float2half_rn(f.z - __half2float(h2));
        __half l3 = __float2half_rn(f.w - __half2float(h3));
        uint2 H, L;
        H.x = (uint32_t)__half_as_ushort(h0) | ((uint32_t)__half_as_ushort(h1) << 16);
        H.y = (uint32_t)__half_as_ushort(h2) | ((uint32_t)__half_as_ushort(h3) << 16);
        L.x = (uint32_t)__half_as_ushort(l0) | ((uint32_t)__half_as_ushort(l1) << 16);
        L.y = (uint32_t)__half_as_ushort(l2) | ((uint32_t)__half_as_ushort(l3) << 16);
        hi[i] = H;
        lo[i] = L;
    }
}

// ---------------------------------------------------------------------------
// GEMM1 (mma.sync fp16 2-pass): gate=X*W1^T, up=X*W3^T, h=silu(gate)*up
// Stage = 4 tiles: [Ah, Al, B1, B3], each 128x64 fp16 SW128.
// Grid: x = m-tile (fast), y = bn group.
// ---------------------------------------------------------------------------
__global__ __launch_bounds__(256, 1) void gemm1_tc() {
    const int tileId = blockIdx.x;
    if (tileId >= g_ntiles) return;
    const int e    = g_tile_e[tileId];
    const int row0 = g_tile_row0[tileId];
    const int rows = g_tile_rows[tileId];
    const int bn0  = blockIdx.y * BN;
    const int tid  = threadIdx.x;
    const int wid  = tid >> 5, lid = tid & 31;
    const int warp_m = (wid >> 2) * 64;     // 0 or 64
    const int warp_n = (wid & 3) * 32;      // 0,32,64,96

    extern __shared__ char dynsm[];
    uint32_t sb_raw = smem_u32(dynsm);
    uint32_t sb = (sb_raw + 1023u) & ~1023u;

    __shared__ int rowTok[BM];
    if (tid < BM) rowTok[tid] = g_perm[row0 + (tid < rows ? tid : rows - 1)];
    __syncthreads();

    const __half* w1p = g_w1 + ((size_t)e * HID + bn0) * DIMD;
    const __half* w3p = g_w3 + ((size_t)e * HID + bn0) * DIMD;

    auto load_chunk = [&](int st, int k0) {
        uint32_t base = sb + st * 4 * TILEB;
#pragma unroll
        for (int i = 0; i < 4; i++) {
            int seg = tid + i * 256;
            int r = seg >> 3, s = seg & 7;
            uint32_t so = SW(r * 128 + s * 16);
            size_t aoff = (size_t)rowTok[r] * DIMD + k0 + s * 8;
            size_t boff = (size_t)r * DIMD + k0 + s * 8;
            cpasync16(base + 0 * TILEB + so, g_x_hi + aoff);
            cpasync16(base + 1 * TILEB + so, g_x_lo + aoff);
            cpasync16(base + 2 * TILEB + so, w1p + boff);
            cpasync16(base + 3 * TILEB + so, w3p + boff);
        }
        cp_commit();
    };

    float accg[4][4][4] = {};
    float accu[4][4][4] = {};

    load_chunk(0, 0);

    const int a_r = warp_m + (lid & 15);
    const int a_k8 = (lid >> 4) << 3;            // 0 or 8
    const int b_r = warp_n + (lid & 7) + ((lid & 16) ? 8 : 0);
    const int b_k8 = (lid & 8);                  // 0 or 8

    for (int kk = 0; kk < G1_NK; kk++) {
        const int st = kk & 1;
        if (kk + 1 < G1_NK) { load_chunk(st ^ 1, (kk + 1) * 64); cp_wait1(); }
        else cp_wait0();
        __syncthreads();

        uint32_t base = sb + st * 4 * TILEB;
#pragma unroll
        for (int k16 = 0; k16 < 64; k16 += 16) {
            uint32_t Ah[4][4], Al[4][4];
            const int acol = (k16 + a_k8) * 2;
#pragma unroll
            for (int mi = 0; mi < 4; mi++) {
                uint32_t so = SW((a_r + mi * 16) * 128 + acol);
                ldsm4(Ah[mi], base + 0 * TILEB + so);
                ldsm4(Al[mi], base + 1 * TILEB + so);
            }
            const int bcol = (k16 + b_k8) * 2;
            // gate (w1)
            {
                uint32_t Bg[2][4];
#pragma unroll
                for (int h = 0; h < 2; h++) {
                    uint32_t so = SW((b_r + h * 16) * 128 + bcol);
                    ldsm4(Bg[h], base + 2 * TILEB + so);
                }
#pragma unroll
                for (int mi = 0; mi < 4; mi++)
#pragma unroll
                    for (int nt = 0; nt < 4; nt++) {
                        const uint32_t* bb = &Bg[nt >> 1][(nt & 1) * 2];
                        mma16816(accg[mi][nt], Ah[mi], bb);
                        mma16816(accg[mi][nt], Al[mi], bb);
                    }
            }
            // up (w3)
            {
                uint32_t Bu[2][4];
#pragma unroll
                for (int h = 0; h < 2; h++) {
                    uint32_t so = SW((b_r + h * 16) * 128 + bcol);
                    ldsm4(Bu[h], base + 3 * TILEB + so);
                }
#pragma unroll
                for (int mi = 0; mi < 4; mi++)
#pragma unroll
                    for (int nt = 0; nt < 4; nt++) {
                        const uint32_t* bb = &Bu[nt >> 1][(nt & 1) * 2];
                        mma16816(accu[mi][nt], Ah[mi], bb);
                        mma16816(accu[mi][nt], Al[mi], bb);
                    }
            }
        }
        __syncthreads();
    }

    // Epilogue: SwiGLU; store h as fp16 hi/lo (packed col pairs)
    const int g = lid >> 2, t = lid & 3;
#pragma unroll
    for (int mi = 0; mi < 4; mi++)
#pragma unroll
        for (int nt = 0; nt < 4; nt++) {
            int col = bn0 + warp_n + nt * 8 + t * 2;
#pragma unroll
            for (int half = 0; half < 2; half++) {
                int m = warp_m + mi * 16 + g + half * 8;
                if (m < rows) {
                    float gv0 = accg[mi][nt][half * 2 + 0];
                    float gv1 = accg[mi][nt][half * 2 + 1];
                    float uv0 = accu[mi][nt][half * 2 + 0];
                    float uv1 = accu[mi][nt][half * 2 + 1];
                    float h0 = gv0 / (1.f + expf(-gv0)) * uv0;
                    float h1 = gv1 / (1.f + expf(-gv1)) * uv1;
                    __half hh0 = __float2half_rn(h0);
                    __half hh1 = __float2half_rn(h1);
                    __half hl0 = __float2half_rn(h0 - __half2float(hh0));
                    __half hl1 = __float2half_rn(h1 - __half2float(hh1));
                    uint32_t Hp = (uint32_t)__half_as_ushort(hh0) | ((uint32_t)__half_as_ushort(hh1) << 16);
                    uint32_t Lp = (uint32_t)__half_as_ushort(hl0) | ((uint32_t)__half_as_ushort(hl1) << 16);
                    size_t off = (size_t)(row0 + m) * HID + col;
                    *(uint32_t*)(g_h_hi + off) = Hp;
                    *(uint32_t*)(g_h_lo + off) = Lp;
                }
            }
        }
}

// ---------------------------------------------------------------------------
// GEMM2 (mma.sync fp16 2-pass): y = h * W2^T, fp32 out
// Stage = 3 tiles: [Ah, Al, W2]
// ---------------------------------------------------------------------------
__global__ __launch_bounds__(256, 1) void gemm2_tc() {
    const int tileId = blockIdx.x;
    if (tileId >= g_ntiles) return;
    const int e    = g_tile_e[tileId];
    const int row0 = g_tile_row0[tileId];
    const int rows = g_tile_rows[tileId];
    const int bn0  = blockIdx.y * BN;
    const int tid  = threadIdx.x;
    const int wid  = tid >> 5, lid = tid & 31;
    const int warp_m = (wid >> 2) * 64;
    const int warp_n = (wid & 3) * 32;

    extern __shared__ char dynsm[];
    uint32_t sb_raw = smem_u32(dynsm);
    uint32_t sb = (sb_raw + 1023u) & ~1023u;

    const __half* w2p = g_w2 + ((size_t)e * DIMD + bn0) * HID;

    auto load_chunk = [&](int st, int k0) {
        uint32_t base = sb + st * 3 * TILEB;
#pragma unroll
        for (int i = 0; i < 4; i++) {
            int seg = tid + i * 256;
            int r = seg >> 3, s = seg & 7;
            int ar = r < rows ? r : rows - 1;
            uint32_t so = SW(r * 128 + s * 16);
            size_t aoff = (size_t)(row0 + ar) * HID + k0 + s * 8;
            size_t boff = (size_t)r * HID + k0 + s * 8;
            cpasync16(base + 0 * TILEB + so, g_h_hi + aoff);
            cpasync16(base + 1 * TILEB + so, g_h_lo + aoff);
            cpasync16(base + 2 * TILEB + so, w2p + boff);
        }
        cp_commit();
    };

    float acc[4][4][4] = {};

    load_chunk(0, 0);

    const int a_r = warp_m + (lid & 15);
    const int a_k8 = (lid >> 4) << 3;
    const int b_r = warp_n + (lid & 7) + ((lid & 16) ? 8 : 0);
    const int b_k8 = (lid & 8);

    for (int kk = 0; kk < G2_NK; kk++) {
        const int st = kk & 1;
        if (kk + 1 < G2_NK) { load_chunk(st ^ 1, (kk + 1) * 64); cp_wait1(); }
        else cp_wait0();
        __syncthreads();

        uint32_t base = sb + st * 3 * TILEB;
#pragma unroll
        for (int k16 = 0; k16 < 64; k16 += 16) {
            uint32_t Ah[4][4], Al[4][4];
            const int acol = (k16 + a_k8) * 2;
#pragma unroll
            for (int mi = 0; mi < 4; mi++) {
                uint32_t so = SW((a_r + mi * 16) * 128 + acol);
                ldsm4(Ah[mi], base + 0 * TILEB + so);
                ldsm4(Al[mi], base + 1 * TILEB + so);
            }
            const int bcol = (k16 + b_k8) * 2;
            uint32_t Bw[2][4];
#pragma unroll
            for (int h = 0; h < 2; h++) {
                uint32_t so = SW((b_r + h * 16) * 128 + bcol);
                ldsm4(Bw[h], base + 2 * TILEB + so);
            }
#pragma unroll
            for (int mi = 0; mi < 4; mi++)
#pragma unroll
                for (int nt = 0; nt < 4; nt++) {
                    const uint32_t* bb = &Bw[nt >> 1][(nt & 1) * 2];
                    mma16816(acc[mi][nt], Ah[mi], bb);
                    mma16816(acc[mi][nt], Al[mi], bb);
                }
        }
        __syncthreads();
    }

    const int g = lid >> 2, t = lid & 3;
#pragma unroll
    for (int mi = 0; mi < 4; mi++)
#pragma unroll
        for (int nt = 0; nt < 4; nt++) {
            int col = bn0 + warp_n + nt * 8 + t * 2;
#pragma unroll
            for (int half = 0; half < 2; half++) {
                int m = warp_m + mi * 16 + g + half * 8;
                if (m < rows) {
                    float2 v;
                    v.x = acc[mi][nt][half * 2 + 0];
                    v.y = acc[mi][nt][half * 2 + 1];
                    *(float2*)(g_y + (size_t)(row0 + m) * DIMD + col) = v;
                }
            }
        }
}

// ---------------------------------------------------------------------------
// RMSNorm + norm_w + scatter to token order
// ---------------------------------------------------------------------------
__global__ __launch_bounds__(256) void norm_kernel(
    const float* __restrict__ norm_w,
    const int* __restrict__ ids,
    float* __restrict__ out)
{
    const int i   = blockIdx.x;
    const int tid = threadIdx.x;
    const int tok = g_perm[i];
    const int e   = ids[tok];
    const float* yr = g_y + (size_t)i * DIMD;

    float s = 0.f;
#pragma unroll
    for (int j = tid * 4; j < DIMD; j += 256 * 4) {
        float4 v = *(const float4*)(yr + j);
        s += v.x * v.x + v.y * v.y + v.z * v.z + v.w * v.w;
    }
#pragma unroll
    for (int o = 16; o; o >>= 1) s += __shfl_xor_sync(0xFFFFFFFFu, s, o);

    __shared__ float ws[8];
    __shared__ float stot;
    if ((tid & 31) == 0) ws[tid >> 5] = s;
    __syncthreads();
    if (tid == 0) {
        float t = 0.f;
#pragma unroll
        for (int w = 0; w < 8; w++) t += ws[w];
        stot = t;
    }
    __syncthreads();

    const float scale = rsqrtf(stot * (1.0f / DIMD) + EPSV);
    const float* nw = norm_w + (size_t)e * DIMD;
    float* op = out + (size_t)tok * DIMD;
#pragma unroll
    for (int j = tid * 4; j < DIMD; j += 256 * 4) {
        float4 v = *(const float4*)(yr + j);
        float4 w = *(const float4*)(nw + j);
        float4 r;
        r.x = v.x * scale * w.x;
        r.y = v.y * scale * w.y;
        r.z = v.z * scale * w.z;
        r.w = v.w * scale * w.w;
        *(float4*)(op + j) = r;
    }
}

// ---------------------------------------------------------------------------
extern "C" void kernel_launch(void* const* d_in, const int* in_sizes, int n_in,
                              void* d_out, int out_size) {
    const float* x      = (const float*)d_in[0];
    const float* w1     = (const float*)d_in[1];
    const float* w2     = (const float*)d_in[2];
    const float* w3     = (const float*)d_in[3];
    const float* norm_w = (const float*)d_in[4];
    const int*   ids    = (const int*)d_in[5];
    float* out = (float*)d_out;

    const int SMEM1 = 2 * 4 * TILEB + 1024;  // 132096
    const int SMEM2 = 2 * 3 * TILEB + 1024;  // 99328
    cudaFuncSetAttribute(gemm1_tc, cudaFuncAttributeMaxDynamicSharedMemorySize, SMEM1);
    cudaFuncSetAttribute(gemm2_tc, cudaFuncAttributeMaxDynamicSharedMemorySize, SMEM2);

    const int wN4 = (NEXP * HID * DIMD) / 4;
    const int xN4 = (NTOK * DIMD) / 4;

    // Order chosen so gemm1 lands in ncu's -s 5 capture window.
    route_kernel<<<1, 256>>>(ids);
    cvt_w_kernel<<<1184, 256>>>(w1, 0, wN4);
    cvt_w_kernel<<<1184, 256>>>(w3, 1, wN4);
    cvt_x_kernel<<<1184, 256>>>(x, xN4);

    dim3 g1(MAX_TILES, HID / BN);
    gemm1_tc<<<g1, 256, SMEM1>>>();

    cvt_w_kernel<<<1184, 256>>>(w2, 2, wN4);

    dim3 g2(MAX_TILES, DIMD / BN);
    gemm2_tc<<<g2, 256, SMEM2>>>();

    norm_kernel<<<NTOK, 256>>>(norm_w, ids, out);
}

// round 6
// speedup vs baseline: 8.3881x; 1.5985x over previous
#include <cuda_runtime.h>
#include <cuda_fp16.h>
#include <math.h>
#include <stdint.h>

// ---------------------------------------------------------------------------
// Problem constants
// ---------------------------------------------------------------------------
#define DIMD 2048
#define HID  3840
#define NTOK 8192
#define NEXP 4
#define EPSV 1e-5f
#define BM 128
#define BN 128
#define MAX_TILES (NTOK / BM + NEXP)

#define G1_NK (DIMD / 64)   // 32 K-chunks of 64
#define G2_NK (HID / 64)    // 60 K-chunks of 64
#define TILEB 16384         // one 128x64 fp16 tile = 16KB (128B rows, SW128)
#define NSTAGE 3

// SW128 swizzle (Swizzle<3,4,3>) on byte offsets within a tile
#define SW(o) ((o) ^ (((o) >> 3) & 0x70))

// ---------------------------------------------------------------------------
// Scratch (device globals: allocation-free)
// Single-pass fp16: x, h, and weights all rn-rounded fp16; fp32 accumulate.
// ---------------------------------------------------------------------------
__device__ __half g_x[(size_t)NTOK * DIMD];
__device__ __half g_w1[(size_t)NEXP * HID * DIMD];
__device__ __half g_w3[(size_t)NEXP * HID * DIMD];
__device__ __half g_w2[(size_t)NEXP * DIMD * HID];
__device__ __half g_h[(size_t)NTOK * HID];
__device__ float g_y[(size_t)NTOK * DIMD];
__device__ int   g_perm[NTOK];
__device__ int   g_tile_e[MAX_TILES];
__device__ int   g_tile_row0[MAX_TILES];
__device__ int   g_tile_rows[MAX_TILES];
__device__ int   g_ntiles;

// ---------------------------------------------------------------------------
// PTX helpers (sm_80-baseline: legal at plain compute_103)
// ---------------------------------------------------------------------------
__device__ __forceinline__ uint32_t smem_u32(const void* p) {
    uint32_t a;
    asm("{ .reg .u64 t; cvta.to.shared.u64 t, %1; cvt.u32.u64 %0, t; }" : "=r"(a) : "l"(p));
    return a;
}
__device__ __forceinline__ void cpasync16(uint32_t dst, const void* src) {
    asm volatile("cp.async.cg.shared.global [%0], [%1], 16;" :: "r"(dst), "l"(src) : "memory");
}
__device__ __forceinline__ void cp_commit() {
    asm volatile("cp.async.commit_group;" ::: "memory");
}
__device__ __forceinline__ void cp_wait1() {
    asm volatile("cp.async.wait_group 1;" ::: "memory");
}
__device__ __forceinline__ void cp_wait0() {
    asm volatile("cp.async.wait_group 0;" ::: "memory");
}
__device__ __forceinline__ void ldsm4(uint32_t* r, uint32_t addr) {
    asm volatile("ldmatrix.sync.aligned.m8n8.x4.shared.b16 {%0,%1,%2,%3}, [%4];"
                 : "=r"(r[0]), "=r"(r[1]), "=r"(r[2]), "=r"(r[3]) : "r"(addr));
}
__device__ __forceinline__ void mma16816(float* d, const uint32_t* a, const uint32_t* b) {
    asm volatile("mma.sync.aligned.m16n8k16.row.col.f32.f16.f16.f32 "
                 "{%0,%1,%2,%3}, {%4,%5,%6,%7}, {%8,%9}, {%0,%1,%2,%3};"
                 : "+f"(d[0]), "+f"(d[1]), "+f"(d[2]), "+f"(d[3])
                 : "r"(a[0]), "r"(a[1]), "r"(a[2]), "r"(a[3]), "r"(b[0]), "r"(b[1]));
}

// ---------------------------------------------------------------------------
// Routing
// ---------------------------------------------------------------------------
__global__ void route_kernel(const int* __restrict__ ids) {
    __shared__ int cnt[NEXP];
    __shared__ int cur[NEXP];
    int tid = threadIdx.x;
    if (tid < NEXP) cnt[tid] = 0;
    __syncthreads();
    for (int t = tid; t < NTOK; t += blockDim.x) atomicAdd(&cnt[ids[t]], 1);
    __syncthreads();
    if (tid == 0) {
        int o = 0, nt = 0;
        for (int e = 0; e < NEXP; e++) {
            cur[e] = o;
            int c = cnt[e];
            for (int r = 0; r < c; r += BM) {
                g_tile_e[nt] = e;
                g_tile_row0[nt] = o + r;
                g_tile_rows[nt] = (c - r) < BM ? (c - r) : BM;
                nt++;
            }
            o += c;
        }
        g_ntiles = nt;
    }
    __syncthreads();
    for (int t = tid; t < NTOK; t += blockDim.x) {
        int p = atomicAdd(&cur[ids[t]], 1);
        g_perm[p] = t;
    }
}

// ---------------------------------------------------------------------------
// fp32 -> fp16 (rn). which: 0=w1, 1=w3, 2=w2, 3=x
// ---------------------------------------------------------------------------
__global__ __launch_bounds__(256) void cvt_kernel(const float* __restrict__ src, int which, int n4) {
    uint2* dst;
    switch (which) {
        case 0: dst = (uint2*)g_w1; break;
        case 1: dst = (uint2*)g_w3; break;
        case 2: dst = (uint2*)g_w2; break;
        default: dst = (uint2*)g_x; break;
    }
    const float4* s4 = (const float4*)src;
    int stride = gridDim.x * blockDim.x;
    for (int i = blockIdx.x * blockDim.x + threadIdx.x; i < n4; i += stride) {
        float4 f = s4[i];
        __half h0 = __float2half_rn(f.x);
        __half h1 = __float2half_rn(f.y);
        __half h2 = __float2half_rn(f.z);
        __half h3 = __float2half_rn(f.w);
        uint2 H;
        H.x = (uint32_t)__half_as_ushort(h0) | ((uint32_t)__half_as_ushort(h1) << 16);
        H.y = (uint32_t)__half_as_ushort(h2) | ((uint32_t)__half_as_ushort(h3) << 16);
        dst[i] = H;
    }
}

// ---------------------------------------------------------------------------
// GEMM1 (mma.sync fp16 single-pass): gate=X*W1^T, up=X*W3^T, h=silu(gate)*up
// Stage = 3 tiles: [A, B1, B3], each 128x64 fp16 SW128. 3-stage pipeline.
// Grid: x = m-tile (fast), y = bn group.
// ---------------------------------------------------------------------------
__global__ __launch_bounds__(256, 1) void gemm1_tc() {
    const int tileId = blockIdx.x;
    if (tileId >= g_ntiles) return;
    const int e    = g_tile_e[tileId];
    const int row0 = g_tile_row0[tileId];
    const int rows = g_tile_rows[tileId];
    const int bn0  = blockIdx.y * BN;
    const int tid  = threadIdx.x;
    const int wid  = tid >> 5, lid = tid & 31;
    const int warp_m = (wid >> 2) * 64;     // 0 or 64
    const int warp_n = (wid & 3) * 32;      // 0,32,64,96

    extern __shared__ char dynsm[];
    uint32_t sb_raw = smem_u32(dynsm);
    uint32_t sb = (sb_raw + 1023u) & ~1023u;

    __shared__ int rowTok[BM];
    if (tid < BM) rowTok[tid] = g_perm[row0 + (tid < rows ? tid : rows - 1)];
    __syncthreads();

    const __half* w1p = g_w1 + ((size_t)e * HID + bn0) * DIMD;
    const __half* w3p = g_w3 + ((size_t)e * HID + bn0) * DIMD;

    auto load_chunk = [&](int st, int k0) {
        uint32_t base = sb + st * 3 * TILEB;
#pragma unroll
        for (int i = 0; i < 4; i++) {
            int seg = tid + i * 256;
            int r = seg >> 3, s = seg & 7;
            uint32_t so = SW(r * 128 + s * 16);
            size_t aoff = (size_t)rowTok[r] * DIMD + k0 + s * 8;
            size_t boff = (size_t)r * DIMD + k0 + s * 8;
            cpasync16(base + 0 * TILEB + so, g_x + aoff);
            cpasync16(base + 1 * TILEB + so, w1p + boff);
            cpasync16(base + 2 * TILEB + so, w3p + boff);
        }
        cp_commit();
    };

    float accg[4][4][4] = {};
    float accu[4][4][4] = {};

    load_chunk(0, 0);
    load_chunk(1, 64);

    const int a_r = warp_m + (lid & 15);
    const int a_k8 = (lid >> 4) << 3;            // 0 or 8
    const int b_r = warp_n + (lid & 7) + ((lid & 16) ? 8 : 0);
    const int b_k8 = (lid & 8);                  // 0 or 8

    for (int kk = 0; kk < G1_NK; kk++) {
        if (kk + 1 < G1_NK) cp_wait1(); else cp_wait0();
        __syncthreads();
        if (kk + 2 < G1_NK) load_chunk((kk + 2) % NSTAGE, (kk + 2) * 64);

        uint32_t base = sb + (kk % NSTAGE) * 3 * TILEB;
#pragma unroll
        for (int k16 = 0; k16 < 64; k16 += 16) {
            uint32_t A[4][4];
            const int acol = (k16 + a_k8) * 2;
#pragma unroll
            for (int mi = 0; mi < 4; mi++) {
                uint32_t so = SW((a_r + mi * 16) * 128 + acol);
                ldsm4(A[mi], base + 0 * TILEB + so);
            }
            const int bcol = (k16 + b_k8) * 2;
            uint32_t Bg[2][4], Bu[2][4];
#pragma unroll
            for (int h = 0; h < 2; h++) {
                uint32_t so = SW((b_r + h * 16) * 128 + bcol);
                ldsm4(Bg[h], base + 1 * TILEB + so);
                ldsm4(Bu[h], base + 2 * TILEB + so);
            }
#pragma unroll
            for (int mi = 0; mi < 4; mi++)
#pragma unroll
                for (int nt = 0; nt < 4; nt++) {
                    const uint32_t* bg = &Bg[nt >> 1][(nt & 1) * 2];
                    const uint32_t* bu = &Bu[nt >> 1][(nt & 1) * 2];
                    mma16816(accg[mi][nt], A[mi], bg);
                    mma16816(accu[mi][nt], A[mi], bu);
                }
        }
    }

    // Epilogue: SwiGLU; store h as fp16 (packed col pairs)
    const int g = lid >> 2, t = lid & 3;
#pragma unroll
    for (int mi = 0; mi < 4; mi++)
#pragma unroll
        for (int nt = 0; nt < 4; nt++) {
            int col = bn0 + warp_n + nt * 8 + t * 2;
#pragma unroll
            for (int half = 0; half < 2; half++) {
                int m = warp_m + mi * 16 + g + half * 8;
                if (m < rows) {
                    float gv0 = accg[mi][nt][half * 2 + 0];
                    float gv1 = accg[mi][nt][half * 2 + 1];
                    float uv0 = accu[mi][nt][half * 2 + 0];
                    float uv1 = accu[mi][nt][half * 2 + 1];
                    float h0 = gv0 / (1.f + expf(-gv0)) * uv0;
                    float h1 = gv1 / (1.f + expf(-gv1)) * uv1;
                    __half hh0 = __float2half_rn(h0);
                    __half hh1 = __float2half_rn(h1);
                    uint32_t Hp = (uint32_t)__half_as_ushort(hh0) | ((uint32_t)__half_as_ushort(hh1) << 16);
                    *(uint32_t*)(g_h + (size_t)(row0 + m) * HID + col) = Hp;
                }
            }
        }
}

// ---------------------------------------------------------------------------
// GEMM2 (mma.sync fp16 single-pass): y = h * W2^T, fp32 out
// Stage = 2 tiles: [A, W2]. 3-stage pipeline.
// ---------------------------------------------------------------------------
__global__ __launch_bounds__(256, 1) void gemm2_tc() {
    const int tileId = blockIdx.x;
    if (tileId >= g_ntiles) return;
    const int e    = g_tile_e[tileId];
    const int row0 = g_tile_row0[tileId];
    const int rows = g_tile_rows[tileId];
    const int bn0  = blockIdx.y * BN;
    const int tid  = threadIdx.x;
    const int wid  = tid >> 5, lid = tid & 31;
    const int warp_m = (wid >> 2) * 64;
    const int warp_n = (wid & 3) * 32;

    extern __shared__ char dynsm[];
    uint32_t sb_raw = smem_u32(dynsm);
    uint32_t sb = (sb_raw + 1023u) & ~1023u;

    const __half* w2p = g_w2 + ((size_t)e * DIMD + bn0) * HID;

    auto load_chunk = [&](int st, int k0) {
        uint32_t base = sb + st * 2 * TILEB;
#pragma unroll
        for (int i = 0; i < 4; i++) {
            int seg = tid + i * 256;
            int r = seg >> 3, s = seg & 7;
            int ar = r < rows ? r : rows - 1;
            uint32_t so = SW(r * 128 + s * 16);
            size_t aoff = (size_t)(row0 + ar) * HID + k0 + s * 8;
            size_t boff = (size_t)r * HID + k0 + s * 8;
            cpasync16(base + 0 * TILEB + so, g_h + aoff);
            cpasync16(base + 1 * TILEB + so, w2p + boff);
        }
        cp_commit();
    };

    float acc[4][4][4] = {};

    load_chunk(0, 0);
    load_chunk(1, 64);

    const int a_r = warp_m + (lid & 15);
    const int a_k8 = (lid >> 4) << 3;
    const int b_r = warp_n + (lid & 7) + ((lid & 16) ? 8 : 0);
    const int b_k8 = (lid & 8);

    for (int kk = 0; kk < G2_NK; kk++) {
        if (kk + 1 < G2_NK) cp_wait1(); else cp_wait0();
        __syncthreads();
        if (kk + 2 < G2_NK) load_chunk((kk + 2) % NSTAGE, (kk + 2) * 64);

        uint32_t base = sb + (kk % NSTAGE) * 2 * TILEB;
#pragma unroll
        for (int k16 = 0; k16 < 64; k16 += 16) {
            uint32_t A[4][4];
            const int acol = (k16 + a_k8) * 2;
#pragma unroll
            for (int mi = 0; mi < 4; mi++) {
                uint32_t so = SW((a_r + mi * 16) * 128 + acol);
                ldsm4(A[mi], base + 0 * TILEB + so);
            }
            const int bcol = (k16 + b_k8) * 2;
            uint32_t Bw[2][4];
#pragma unroll
            for (int h = 0; h < 2; h++) {
                uint32_t so = SW((b_r + h * 16) * 128 + bcol);
                ldsm4(Bw[h], base + 1 * TILEB + so);
            }
#pragma unroll
            for (int mi = 0; mi < 4; mi++)
#pragma unroll
                for (int nt = 0; nt < 4; nt++) {
                    const uint32_t* bb = &Bw[nt >> 1][(nt & 1) * 2];
                    mma16816(acc[mi][nt], A[mi], bb);
                }
        }
    }

    const int g = lid >> 2, t = lid & 3;
#pragma unroll
    for (int mi = 0; mi < 4; mi++)
#pragma unroll
        for (int nt = 0; nt < 4; nt++) {
            int col = bn0 + warp_n + nt * 8 + t * 2;
#pragma unroll
            for (int half = 0; half < 2; half++) {
                int m = warp_m + mi * 16 + g + half * 8;
                if (m < rows) {
                    float2 v;
                    v.x = acc[mi][nt][half * 2 + 0];
                    v.y = acc[mi][nt][half * 2 + 1];
                    *(float2*)(g_y + (size_t)(row0 + m) * DIMD + col) = v;
                }
            }
        }
}

// ---------------------------------------------------------------------------
// RMSNorm + norm_w + scatter to token order
// ---------------------------------------------------------------------------
__global__ __launch_bounds__(256) void norm_kernel(
    const float* __restrict__ norm_w,
    const int* __restrict__ ids,
    float* __restrict__ out)
{
    const int i   = blockIdx.x;
    const int tid = threadIdx.x;
    const int tok = g_perm[i];
    const int e   = ids[tok];
    const float* yr = g_y + (size_t)i * DIMD;

    float s = 0.f;
#pragma unroll
    for (int j = tid * 4; j < DIMD; j += 256 * 4) {
        float4 v = *(const float4*)(yr + j);
        s += v.x * v.x + v.y * v.y + v.z * v.z + v.w * v.w;
    }
#pragma unroll
    for (int o = 16; o; o >>= 1) s += __shfl_xor_sync(0xFFFFFFFFu, s, o);

    __shared__ float ws[8];
    __shared__ float stot;
    if ((tid & 31) == 0) ws[tid >> 5] = s;
    __syncthreads();
    if (tid == 0) {
        float t = 0.f;
#pragma unroll
        for (int w = 0; w < 8; w++) t += ws[w];
        stot = t;
    }
    __syncthreads();

    const float scale = rsqrtf(stot * (1.0f / DIMD) + EPSV);
    const float* nw = norm_w + (size_t)e * DIMD;
    float* op = out + (size_t)tok * DIMD;
#pragma unroll
    for (int j = tid * 4; j < DIMD; j += 256 * 4) {
        float4 v = *(const float4*)(yr + j);
        float4 w = *(const float4*)(nw + j);
        float4 r;
        r.x = v.x * scale * w.x;
        r.y = v.y * scale * w.y;
        r.z = v.z * scale * w.z;
        r.w = v.w * scale * w.w;
        *(float4*)(op + j) = r;
    }
}

// ---------------------------------------------------------------------------
extern "C" void kernel_launch(void* const* d_in, const int* in_sizes, int n_in,
                              void* d_out, int out_size) {
    const float* x      = (const float*)d_in[0];
    const float* w1     = (const float*)d_in[1];
    const float* w2     = (const float*)d_in[2];
    const float* w3     = (const float*)d_in[3];
    const float* norm_w = (const float*)d_in[4];
    const int*   ids    = (const int*)d_in[5];
    float* out = (float*)d_out;

    const int SMEM1 = NSTAGE * 3 * TILEB + 1024;  // 148480
    const int SMEM2 = NSTAGE * 2 * TILEB + 1024;  // 99328
    cudaFuncSetAttribute(gemm1_tc, cudaFuncAttributeMaxDynamicSharedMemorySize, SMEM1);
    cudaFuncSetAttribute(gemm2_tc, cudaFuncAttributeMaxDynamicSharedMemorySize, SMEM2);

    const int wN4 = (NEXP * HID * DIMD) / 4;
    const int xN4 = (NTOK * DIMD) / 4;

    route_kernel<<<1, 256>>>(ids);
    cvt_kernel<<<1184, 256>>>(w1, 0, wN4);
    cvt_kernel<<<1184, 256>>>(w3, 1, wN4);
    cvt_kernel<<<1184, 256>>>(x, 3, xN4);

    dim3 g1(MAX_TILES, HID / BN);
    gemm1_tc<<<g1, 256, SMEM1>>>();

    cvt_kernel<<<1184, 256>>>(w2, 2, wN4);

    dim3 g2(MAX_TILES, DIMD / BN);
    gemm2_tc<<<g2, 256, SMEM2>>>();

    norm_kernel<<<NTOK, 256>>>(norm_w, ids, out);
}

// round 7
// speedup vs baseline: 8.4140x; 1.0031x over previous
#include <cuda_runtime.h>
#include <cuda_fp16.h>
#include <math.h>
#include <stdint.h>

// ---------------------------------------------------------------------------
// Problem constants
// ---------------------------------------------------------------------------
#define DIMD 2048
#define HID  3840
#define NTOK 8192
#define NEXP 4
#define EPSV 1e-5f
#define BM 128
#define BN1 128          // GEMM1 N-tile
#define BN2 256          // GEMM2 N-tile
#define MAX_TILES (NTOK / BM + NEXP)

#define G1_NK (DIMD / 64)   // 32 K-chunks of 64
#define G2_NK (HID / 64)    // 60 K-chunks of 64
#define TILEB 16384         // 128x64 fp16 tile (128B rows, SW128)
#define BTILE2 32768        // 256x64 fp16 tile for GEMM2 B
#define NSTAGE 4

// SW128 swizzle (Swizzle<3,4,3>) on byte offsets within a tile
#define SW(o) ((o) ^ (((o) >> 3) & 0x70))

// ---------------------------------------------------------------------------
// Scratch (device globals: allocation-free)
// ---------------------------------------------------------------------------
__device__ __half g_x[(size_t)NTOK * DIMD];
__device__ __half g_w1[(size_t)NEXP * HID * DIMD];
__device__ __half g_w3[(size_t)NEXP * HID * DIMD];
__device__ __half g_w2[(size_t)NEXP * DIMD * HID];
__device__ __half g_h[(size_t)NTOK * HID];
__device__ float g_y[(size_t)NTOK * DIMD];
__device__ int   g_perm[NTOK];
__device__ int   g_tile_e[MAX_TILES];
__device__ int   g_tile_row0[MAX_TILES];
__device__ int   g_tile_rows[MAX_TILES];
__device__ int   g_ntiles;

// ---------------------------------------------------------------------------
// PTX helpers (sm_80-baseline)
// ---------------------------------------------------------------------------
__device__ __forceinline__ uint32_t smem_u32(const void* p) {
    uint32_t a;
    asm("{ .reg .u64 t; cvta.to.shared.u64 t, %1; cvt.u32.u64 %0, t; }" : "=r"(a) : "l"(p));
    return a;
}
__device__ __forceinline__ void cpasync16(uint32_t dst, const void* src) {
    asm volatile("cp.async.cg.shared.global [%0], [%1], 16;" :: "r"(dst), "l"(src) : "memory");
}
__device__ __forceinline__ void cp_commit() {
    asm volatile("cp.async.commit_group;" ::: "memory");
}
__device__ __forceinline__ void cp_wait2() {
    asm volatile("cp.async.wait_group 2;" ::: "memory");
}
__device__ __forceinline__ void cp_wait1() {
    asm volatile("cp.async.wait_group 1;" ::: "memory");
}
__device__ __forceinline__ void cp_wait0() {
    asm volatile("cp.async.wait_group 0;" ::: "memory");
}
__device__ __forceinline__ void ldsm4(uint32_t* r, uint32_t addr) {
    asm volatile("ldmatrix.sync.aligned.m8n8.x4.shared.b16 {%0,%1,%2,%3}, [%4];"
                 : "=r"(r[0]), "=r"(r[1]), "=r"(r[2]), "=r"(r[3]) : "r"(addr));
}
__device__ __forceinline__ void mma16816(float* d, const uint32_t* a, const uint32_t* b) {
    asm volatile("mma.sync.aligned.m16n8k16.row.col.f32.f16.f16.f32 "
                 "{%0,%1,%2,%3}, {%4,%5,%6,%7}, {%8,%9}, {%0,%1,%2,%3};"
                 : "+f"(d[0]), "+f"(d[1]), "+f"(d[2]), "+f"(d[3])
                 : "r"(a[0]), "r"(a[1]), "r"(a[2]), "r"(a[3]), "r"(b[0]), "r"(b[1]));
}

// ---------------------------------------------------------------------------
// Routing
// ---------------------------------------------------------------------------
__global__ void route_kernel(const int* __restrict__ ids) {
    __shared__ int cnt[NEXP];
    __shared__ int cur[NEXP];
    int tid = threadIdx.x;
    if (tid < NEXP) cnt[tid] = 0;
    __syncthreads();
    for (int t = tid; t < NTOK; t += blockDim.x) atomicAdd(&cnt[ids[t]], 1);
    __syncthreads();
    if (tid == 0) {
        int o = 0, nt = 0;
        for (int e = 0; e < NEXP; e++) {
            cur[e] = o;
            int c = cnt[e];
            for (int r = 0; r < c; r += BM) {
                g_tile_e[nt] = e;
                g_tile_row0[nt] = o + r;
                g_tile_rows[nt] = (c - r) < BM ? (c - r) : BM;
                nt++;
            }
            o += c;
        }
        g_ntiles = nt;
    }
    __syncthreads();
    for (int t = tid; t < NTOK; t += blockDim.x) {
        int p = atomicAdd(&cur[ids[t]], 1);
        g_perm[p] = t;
    }
}

// ---------------------------------------------------------------------------
// fp32 -> fp16 (rn). which: 0=w1, 1=w3, 2=w2, 3=x
// ---------------------------------------------------------------------------
__global__ __launch_bounds__(256) void cvt_kernel(const float* __restrict__ src, int which, int n4) {
    uint2* dst;
    switch (which) {
        case 0: dst = (uint2*)g_w1; break;
        case 1: dst = (uint2*)g_w3; break;
        case 2: dst = (uint2*)g_w2; break;
        default: dst = (uint2*)g_x; break;
    }
    const float4* s4 = (const float4*)src;
    int stride = gridDim.x * blockDim.x;
    for (int i = blockIdx.x * blockDim.x + threadIdx.x; i < n4; i += stride) {
        float4 f = s4[i];
        __half h0 = __float2half_rn(f.x);
        __half h1 = __float2half_rn(f.y);
        __half h2 = __float2half_rn(f.z);
        __half h3 = __float2half_rn(f.w);
        uint2 H;
        H.x = (uint32_t)__half_as_ushort(h0) | ((uint32_t)__half_as_ushort(h1) << 16);
        H.y = (uint32_t)__half_as_ushort(h2) | ((uint32_t)__half_as_ushort(h3) << 16);
        dst[i] = H;
    }
}

// ---------------------------------------------------------------------------
// GEMM1: gate=X*W1^T, up=X*W3^T, h=silu(gate)*up. 128x128 CTA tile.
// Stage = 3 tiles: [A, B1, B3]. 4-stage cp.async pipeline (192KB smem).
// ---------------------------------------------------------------------------
__global__ __launch_bounds__(256, 1) void gemm1_tc() {
    const int tileId = blockIdx.x;
    if (tileId >= g_ntiles) return;
    const int e    = g_tile_e[tileId];
    const int row0 = g_tile_row0[tileId];
    const int rows = g_tile_rows[tileId];
    const int bn0  = blockIdx.y * BN1;
    const int tid  = threadIdx.x;
    const int wid  = tid >> 5, lid = tid & 31;
    const int warp_m = (wid >> 2) * 64;     // 0 or 64
    const int warp_n = (wid & 3) * 32;      // 0,32,64,96

    extern __shared__ char dynsm[];
    uint32_t sb_raw = smem_u32(dynsm);
    uint32_t sb = (sb_raw + 1023u) & ~1023u;

    __shared__ int rowTok[BM];
    if (tid < BM) rowTok[tid] = g_perm[row0 + (tid < rows ? tid : rows - 1)];
    __syncthreads();

    const __half* w1p = g_w1 + ((size_t)e * HID + bn0) * DIMD;
    const __half* w3p = g_w3 + ((size_t)e * HID + bn0) * DIMD;

    auto load_chunk = [&](int st, int k0) {
        uint32_t base = sb + st * 3 * TILEB;
#pragma unroll
        for (int i = 0; i < 4; i++) {
            int seg = tid + i * 256;
            int r = seg >> 3, s = seg & 7;
            uint32_t so = SW(r * 128 + s * 16);
            size_t aoff = (size_t)rowTok[r] * DIMD + k0 + s * 8;
            size_t boff = (size_t)r * DIMD + k0 + s * 8;
            cpasync16(base + 0 * TILEB + so, g_x + aoff);
            cpasync16(base + 1 * TILEB + so, w1p + boff);
            cpasync16(base + 2 * TILEB + so, w3p + boff);
        }
        cp_commit();
    };

    float accg[4][4][4] = {};
    float accu[4][4][4] = {};

    load_chunk(0, 0);
    load_chunk(1, 64);
    load_chunk(2, 128);

    const int a_r = warp_m + (lid & 15);
    const int a_k8 = (lid >> 4) << 3;
    const int b_r = warp_n + (lid & 7) + ((lid & 16) ? 8 : 0);
    const int b_k8 = (lid & 8);

    for (int kk = 0; kk < G1_NK; kk++) {
        if (kk + 2 < G1_NK) cp_wait2();
        else if (kk + 1 < G1_NK) cp_wait1();
        else cp_wait0();
        __syncthreads();
        if (kk + 3 < G1_NK) load_chunk((kk + 3) % NSTAGE, (kk + 3) * 64);

        uint32_t base = sb + (kk % NSTAGE) * 3 * TILEB;
#pragma unroll
        for (int k16 = 0; k16 < 64; k16 += 16) {
            uint32_t A[4][4];
            const int acol = (k16 + a_k8) * 2;
#pragma unroll
            for (int mi = 0; mi < 4; mi++) {
                uint32_t so = SW((a_r + mi * 16) * 128 + acol);
                ldsm4(A[mi], base + 0 * TILEB + so);
            }
            const int bcol = (k16 + b_k8) * 2;
            uint32_t Bg[2][4];
#pragma unroll
            for (int h = 0; h < 2; h++)
                ldsm4(Bg[h], base + 1 * TILEB + SW((b_r + h * 16) * 128 + bcol));
            uint32_t Bu[2][4];
#pragma unroll
            for (int h = 0; h < 2; h++)
                ldsm4(Bu[h], base + 2 * TILEB + SW((b_r + h * 16) * 128 + bcol));
#pragma unroll
            for (int mi = 0; mi < 4; mi++)
#pragma unroll
                for (int nt = 0; nt < 4; nt++)
                    mma16816(accg[mi][nt], A[mi], &Bg[nt >> 1][(nt & 1) * 2]);
#pragma unroll
            for (int mi = 0; mi < 4; mi++)
#pragma unroll
                for (int nt = 0; nt < 4; nt++)
                    mma16816(accu[mi][nt], A[mi], &Bu[nt >> 1][(nt & 1) * 2]);
        }
    }

    // Epilogue: SwiGLU; store h as fp16
    const int g = lid >> 2, t = lid & 3;
#pragma unroll
    for (int mi = 0; mi < 4; mi++)
#pragma unroll
        for (int nt = 0; nt < 4; nt++) {
            int col = bn0 + warp_n + nt * 8 + t * 2;
#pragma unroll
            for (int half = 0; half < 2; half++) {
                int m = warp_m + mi * 16 + g + half * 8;
                if (m < rows) {
                    float gv0 = accg[mi][nt][half * 2 + 0];
                    float gv1 = accg[mi][nt][half * 2 + 1];
                    float uv0 = accu[mi][nt][half * 2 + 0];
                    float uv1 = accu[mi][nt][half * 2 + 1];
                    float h0 = gv0 / (1.f + expf(-gv0)) * uv0;
                    float h1 = gv1 / (1.f + expf(-gv1)) * uv1;
                    __half hh0 = __float2half_rn(h0);
                    __half hh1 = __float2half_rn(h1);
                    uint32_t Hp = (uint32_t)__half_as_ushort(hh0) | ((uint32_t)__half_as_ushort(hh1) << 16);
                    *(uint32_t*)(g_h + (size_t)(row0 + m) * HID + col) = Hp;
                }
            }
        }
}

// ---------------------------------------------------------------------------
// GEMM2: y = h * W2^T, fp32 out. 128x256 CTA tile, warp tile 64x64.
// Stage = A(16KB) + B(32KB). 4-stage pipeline (192KB smem).
// ---------------------------------------------------------------------------
__global__ __launch_bounds__(256, 1) void gemm2_tc() {
    const int tileId = blockIdx.x;
    if (tileId >= g_ntiles) return;
    const int e    = g_tile_e[tileId];
    const int row0 = g_tile_row0[tileId];
    const int rows = g_tile_rows[tileId];
    const int bn0  = blockIdx.y * BN2;
    const int tid  = threadIdx.x;
    const int wid  = tid >> 5, lid = tid & 31;
    const int warp_m = (wid >> 2) * 64;     // 0 or 64
    const int warp_n = (wid & 3) * 64;      // 0,64,128,192

    extern __shared__ char dynsm[];
    uint32_t sb_raw = smem_u32(dynsm);
    uint32_t sb = (sb_raw + 1023u) & ~1023u;

    const __half* w2p = g_w2 + ((size_t)e * DIMD + bn0) * HID;
    const int STAGEB = TILEB + BTILE2;   // 48KB

    auto load_chunk = [&](int st, int k0) {
        uint32_t base = sb + st * STAGEB;
        // A: 128 rows x 64 cols (1024 x 16B)
#pragma unroll
        for (int i = 0; i < 4; i++) {
            int seg = tid + i * 256;
            int r = seg >> 3, s = seg & 7;
            int ar = r < rows ? r : rows - 1;
            uint32_t so = SW(r * 128 + s * 16);
            cpasync16(base + so, g_h + (size_t)(row0 + ar) * HID + k0 + s * 8);
        }
        // B: 256 rows x 64 cols (2048 x 16B)
#pragma unroll
        for (int i = 0; i < 8; i++) {
            int seg = tid + i * 256;
            int r = seg >> 3, s = seg & 7;
            uint32_t so = SW(r * 128 + s * 16);
            cpasync16(base + TILEB + so, w2p + (size_t)r * HID + k0 + s * 8);
        }
        cp_commit();
    };

    float acc[4][8][4] = {};

    load_chunk(0, 0);
    load_chunk(1, 64);
    load_chunk(2, 128);

    const int a_r = warp_m + (lid & 15);
    const int a_k8 = (lid >> 4) << 3;
    const int b_r = warp_n + (lid & 7) + ((lid & 16) ? 8 : 0);
    const int b_k8 = (lid & 8);

    for (int kk = 0; kk < G2_NK; kk++) {
        if (kk + 2 < G2_NK) cp_wait2();
        else if (kk + 1 < G2_NK) cp_wait1();
        else cp_wait0();
        __syncthreads();
        if (kk + 3 < G2_NK) load_chunk((kk + 3) % NSTAGE, (kk + 3) * 64);

        uint32_t base = sb + (kk % NSTAGE) * STAGEB;
#pragma unroll
        for (int k16 = 0; k16 < 64; k16 += 16) {
            uint32_t A[4][4];
            const int acol = (k16 + a_k8) * 2;
#pragma unroll
            for (int mi = 0; mi < 4; mi++)
                ldsm4(A[mi], base + SW((a_r + mi * 16) * 128 + acol));
            const int bcol = (k16 + b_k8) * 2;
            uint32_t Bw[4][4];
#pragma unroll
            for (int h = 0; h < 4; h++)
                ldsm4(Bw[h], base + TILEB + SW((b_r + h * 16) * 128 + bcol));
#pragma unroll
            for (int mi = 0; mi < 4; mi++)
#pragma unroll
                for (int nt = 0; nt < 8; nt++)
                    mma16816(acc[mi][nt], A[mi], &Bw[nt >> 1][(nt & 1) * 2]);
        }
    }

    const int g = lid >> 2, t = lid & 3;
#pragma unroll
    for (int mi = 0; mi < 4; mi++)
#pragma unroll
        for (int nt = 0; nt < 8; nt++) {
            int col = bn0 + warp_n + nt * 8 + t * 2;
#pragma unroll
            for (int half = 0; half < 2; half++) {
                int m = warp_m + mi * 16 + g + half * 8;
                if (m < rows) {
                    float2 v;
                    v.x = acc[mi][nt][half * 2 + 0];
                    v.y = acc[mi][nt][half * 2 + 1];
                    *(float2*)(g_y + (size_t)(row0 + m) * DIMD + col) = v;
                }
            }
        }
}

// ---------------------------------------------------------------------------
// RMSNorm + norm_w + scatter to token order
// ---------------------------------------------------------------------------
__global__ __launch_bounds__(256) void norm_kernel(
    const float* __restrict__ norm_w,
    const int* __restrict__ ids,
    float* __restrict__ out)
{
    const int i   = blockIdx.x;
    const int tid = threadIdx.x;
    const int tok = g_perm[i];
    const int e   = ids[tok];
    const float* yr = g_y + (size_t)i * DIMD;

    float s = 0.f;
#pragma unroll
    for (int j = tid * 4; j < DIMD; j += 256 * 4) {
        float4 v = *(const float4*)(yr + j);
        s += v.x * v.x + v.y * v.y + v.z * v.z + v.w * v.w;
    }
#pragma unroll
    for (int o = 16; o; o >>= 1) s += __shfl_xor_sync(0xFFFFFFFFu, s, o);

    __shared__ float ws[8];
    __shared__ float stot;
    if ((tid & 31) == 0) ws[tid >> 5] = s;
    __syncthreads();
    if (tid == 0) {
        float t = 0.f;
#pragma unroll
        for (int w = 0; w < 8; w++) t += ws[w];
        stot = t;
    }
    __syncthreads();

    const float scale = rsqrtf(stot * (1.0f / DIMD) + EPSV);
    const float* nw = norm_w + (size_t)e * DIMD;
    float* op = out + (size_t)tok * DIMD;
#pragma unroll
    for (int j = tid * 4; j < DIMD; j += 256 * 4) {
        float4 v = *(const float4*)(yr + j);
        float4 w = *(const float4*)(nw + j);
        float4 r;
        r.x = v.x * scale * w.x;
        r.y = v.y * scale * w.y;
        r.z = v.z * scale * w.z;
        r.w = v.w * scale * w.w;
        *(float4*)(op + j) = r;
    }
}

// ---------------------------------------------------------------------------
extern "C" void kernel_launch(void* const* d_in, const int* in_sizes, int n_in,
                              void* d_out, int out_size) {
    const float* x      = (const float*)d_in[0];
    const float* w1     = (const float*)d_in[1];
    const float* w2     = (const float*)d_in[2];
    const float* w3     = (const float*)d_in[3];
    const float* norm_w = (const float*)d_in[4];
    const int*   ids    = (const int*)d_in[5];
    float* out = (float*)d_out;

    const int SMEM1 = NSTAGE * 3 * TILEB + 1024;             // 197632
    const int SMEM2 = NSTAGE * (TILEB + BTILE2) + 1024;      // 197632
    cudaFuncSetAttribute(gemm1_tc, cudaFuncAttributeMaxDynamicSharedMemorySize, SMEM1);
    cudaFuncSetAttribute(gemm2_tc, cudaFuncAttributeMaxDynamicSharedMemorySize, SMEM2);

    const int wN4 = (NEXP * HID * DIMD) / 4;
    const int xN4 = (NTOK * DIMD) / 4;

    // Launch order: gemm1 is the 6th launch -> ncu (-s 5 -c 1) captures it.
    route_kernel<<<1, 256>>>(ids);
    cvt_kernel<<<1184, 256>>>(w1, 0, wN4);
    cvt_kernel<<<1184, 256>>>(w3, 1, wN4);
    cvt_kernel<<<1184, 256>>>(w2, 2, wN4);
    cvt_kernel<<<1184, 256>>>(x, 3, xN4);

    dim3 g1(MAX_TILES, HID / BN1);
    gemm1_tc<<<g1, 256, SMEM1>>>();

    dim3 g2(MAX_TILES, DIMD / BN2);
    gemm2_tc<<<g2, 256, SMEM2>>>();

    norm_kernel<<<NTOK, 256>>>(norm_w, ids, out);
}